// round 4
// baseline (speedup 1.0000x reference)
#include <cuda_runtime.h>
#include <cstdint>
#include <math.h>

#define BB 16
#define LL 2048
#define DIN 64
#define HH 256
#define NH 32
#define NLAYERS 4
#define DM1 128
#define DM2 64
#define DOUT 32

#define MROWS (BB*LL)          // 32768
#define NMBLK (MROWS/128)      // 256 row blocks

// Scratch (allocation-free contract: __device__ globals)
__device__ float g_h    [MROWS*HH];              // hidden state (B*L, H)
__device__ float g_zr   [MROWS*HH];              // glu + residual (pre-LN)
// A fragments: [mblock(256)][kstep(32)][mtile(8)][lane(32)][reg(4)][hi,lo]
__device__ float g_afrag[(size_t)NMBLK*32*8*32*4*2];
// B fragments: [layer][nblock(4)][kstep(32)][ntile(16)][lane(32)][reg(2)][hi,lo]
__device__ float g_wfrag[(size_t)NLAYERS*4*32*16*32*2*2];
__device__ float g_pool [BB*HH];

// ---------------------------------------------------------------------------
// helpers
// ---------------------------------------------------------------------------
__device__ __forceinline__ uint32_t smem_u32(const void* p) {
    uint32_t a;
    asm("{ .reg .u64 t; cvta.to.shared.u64 t, %1; cvt.u32.u64 %0, t; }"
        : "=r"(a) : "l"(p));
    return a;
}
__device__ __forceinline__ float tf32r(float x) {
    uint32_t u;
    asm("cvt.rna.tf32.f32 %0, %1;" : "=r"(u) : "f"(x));
    return __uint_as_float(u);
}
__device__ __forceinline__ void cp16(uint32_t dst, const float* src) {
    asm volatile("cp.async.cg.shared.global [%0], [%1], 16;"
                 :: "r"(dst), "l"(src));
}
__device__ __forceinline__ void mma_tf32(float* d, const uint32_t* a,
                                         uint32_t b0, uint32_t b1) {
    asm volatile(
        "mma.sync.aligned.m16n8k8.row.col.f32.tf32.tf32.f32 "
        "{%0,%1,%2,%3}, {%4,%5,%6,%7}, {%8,%9}, {%0,%1,%2,%3};"
        : "+f"(d[0]), "+f"(d[1]), "+f"(d[2]), "+f"(d[3])
        : "r"(a[0]), "r"(a[1]), "r"(a[2]), "r"(a[3]), "r"(b0), "r"(b1));
}

// ---------------------------------------------------------------------------
// Weight prep: 3xTF32 split of w_out into fragment-ordered g_wfrag.
// w layout: [layer][o(512)][h(256)].
// frag index: nb=(o&255)>>6, nt=((o&63)>>3)|((o>>8)<<3), lane=((o&7)<<2)|(h&3),
//             ks=h>>3, reg=(h>>2)&1.
// ---------------------------------------------------------------------------
__global__ __launch_bounds__(256) void prep_w_kernel(const float* __restrict__ w) {
    int i = blockIdx.x * 256 + threadIdx.x;
    if (i >= NLAYERS * 512 * HH) return;
    int h = i & 255;
    int o = (i >> 8) & 511;
    int layer = i >> 17;
    float v = w[i];
    float hi = tf32r(v);
    float lo = tf32r(v - hi);
    int nb = (o & 255) >> 6;
    int nt = ((o & 63) >> 3) | ((o >> 8) << 3);
    int lane = ((o & 7) << 2) | (h & 3);
    int ks = h >> 3;
    int reg = (h >> 2) & 1;
    size_t off = ((((((size_t)layer * 4 + nb) * 32 + ks) * 16 + nt) * 32 + lane) * 2 + reg) * 2;
    g_wfrag[off] = hi;
    g_wfrag[off + 1] = lo;
}

// ---------------------------------------------------------------------------
// Encoder: g_h[m, n] = x[m, :64] @ enc_w[:, n] + enc_b[n]  (fp32 SIMT, small)
// ---------------------------------------------------------------------------
__global__ __launch_bounds__(256) void encoder_kernel(
        const float* __restrict__ X, const float* __restrict__ W,
        const float* __restrict__ bias) {
    __shared__ float As[64][36];
    __shared__ float Bs[32][68];
    int row0 = blockIdx.x * 64;
    int n0   = blockIdx.y * 64;
    int tid = threadIdx.x;
    int tx = tid & 15, ty = tid >> 4;
    float acc[4][4] = {};
    for (int k0 = 0; k0 < DIN; k0 += 32) {
        #pragma unroll
        for (int p = 0; p < 2; p++) {
            int q = tid + p * 256;
            int r = q >> 3, kq = q & 7;
            float4 v = *(const float4*)&X[(row0 + r) * DIN + k0 + kq * 4];
            *(float4*)&As[r][kq * 4] = v;
        }
        #pragma unroll
        for (int p = 0; p < 2; p++) {
            int q = tid + p * 256;
            int kk = q >> 4, nq = q & 15;
            float4 v = *(const float4*)&W[(k0 + kk) * HH + n0 + nq * 4];
            *(float4*)&Bs[kk][nq * 4] = v;
        }
        __syncthreads();
        #pragma unroll
        for (int k = 0; k < 32; k++) {
            float a[4];
            #pragma unroll
            for (int i = 0; i < 4; i++) a[i] = As[ty * 4 + i][k];
            float4 bv = *(const float4*)&Bs[k][tx * 4];
            float bj[4] = {bv.x, bv.y, bv.z, bv.w};
            #pragma unroll
            for (int i = 0; i < 4; i++)
                #pragma unroll
                for (int j = 0; j < 4; j++)
                    acc[i][j] = fmaf(a[i], bj[j], acc[i][j]);
        }
        __syncthreads();
    }
    #pragma unroll
    for (int i = 0; i < 4; i++) {
        int m = row0 + ty * 4 + i;
        #pragma unroll
        for (int j = 0; j < 4; j++) {
            int n = n0 + tx * 4 + j;
            g_h[m * HH + n] = acc[i][j] + bias[n];
        }
    }
}

// ---------------------------------------------------------------------------
// S4D scan fused with D-skip + exact GELU; writes fragment-ordered TF32
// hi/lo pairs into g_afrag.
// ---------------------------------------------------------------------------
#define SCAN_T 128
__global__ __launch_bounds__(128) void scan_kernel(
        const float* __restrict__ log_dt, const float* __restrict__ C_re,
        const float* __restrict__ C_im,   const float* __restrict__ log_A_real,
        const float* __restrict__ A_imag, const float* __restrict__ D_skip,
        int layer) {
    __shared__ float s_in [SCAN_T * 16];
    __shared__ float s_out[SCAN_T * 16];
    int b   = blockIdx.x;
    int ch0 = blockIdx.y * 16;
    int tid = threadIdx.x;
    int warp = tid >> 5, lane = tid & 31;
    int g = lane >> 3, j = lane & 7;
    int c_local = warp * 4 + g;
    int ch = ch0 + c_local;

    float dt  = expf(log_dt[layer * HH + ch]);
    float dsk = D_skip[layer * HH + ch];
    float w_re[4], w_im[4], ck_re[4], ck_im[4], s_re[4], s_im[4];
    #pragma unroll
    for (int k = 0; k < 4; k++) {
        int n = j * 4 + k;
        int idx = (layer * HH + ch) * NH + n;
        float Are = -expf(log_A_real[idx]);
        float Aim = A_imag[idx];
        float er  = expf(dt * Are);
        float wre = er * cosf(dt * Aim);
        float wim = er * sinf(dt * Aim);
        w_re[k] = wre; w_im[k] = wim;
        float nre = wre - 1.0f, nim = wim;
        float inv = 1.0f / (Are * Are + Aim * Aim);
        float ire = Are * inv, iim = -Aim * inv;
        float tre = nre * ire - nim * iim;
        float tim = nre * iim + nim * ire;
        float cre = C_re[idx], cim = C_im[idx];
        ck_re[k] = 2.0f * (cre * tre - cim * tim);
        ck_im[k] = 2.0f * (cre * tim + cim * tre);
        s_re[k] = 0.0f; s_im[k] = 0.0f;
    }

    const float* hin = g_h + (size_t)b * LL * HH;

    for (int l0 = 0; l0 < LL; l0 += SCAN_T) {
        #pragma unroll
        for (int p = 0; p < 4; p++) {
            int q = tid + p * 128;
            int t = q >> 2, cq = q & 3;
            float4 v = *(const float4*)&hin[(l0 + t) * HH + ch0 + cq * 4];
            *(float4*)&s_in[t * 16 + cq * 4] = v;
        }
        __syncthreads();
        #pragma unroll 4
        for (int t = 0; t < SCAN_T; t++) {
            float u = s_in[t * 16 + c_local];
            float pacc = 0.0f;
            #pragma unroll
            for (int k = 0; k < 4; k++) {
                float nr = fmaf(w_re[k], s_re[k], u);
                nr = fmaf(-w_im[k], s_im[k], nr);
                float ni = w_re[k] * s_im[k];
                ni = fmaf(w_im[k], s_re[k], ni);
                s_re[k] = nr; s_im[k] = ni;
                pacc = fmaf(ck_re[k], nr, pacc);
                pacc = fmaf(-ck_im[k], ni, pacc);
            }
            pacc += __shfl_xor_sync(0xffffffffu, pacc, 1);
            pacc += __shfl_xor_sync(0xffffffffu, pacc, 2);
            pacc += __shfl_xor_sync(0xffffffffu, pacc, 4);
            if (j == 0)
                s_out[t * 16 + c_local] = fmaf(u, dsk, pacc);
        }
        __syncthreads();
        #pragma unroll
        for (int p = 0; p < 4; p++) {
            int q = tid + p * 128;
            int t = q >> 2, cq = q & 3;
            float4 v = *(const float4*)&s_out[t * 16 + cq * 4];
            v.x = 0.5f * v.x * (1.0f + erff(v.x * 0.70710678118654752f));
            v.y = 0.5f * v.y * (1.0f + erff(v.y * 0.70710678118654752f));
            v.z = 0.5f * v.z * (1.0f + erff(v.z * 0.70710678118654752f));
            v.w = 0.5f * v.w * (1.0f + erff(v.w * 0.70710678118654752f));
            int m  = b * LL + l0 + t;
            int chb = ch0 + cq * 4;            // aligned 4 -> same kstep/reg pair
            int mbk = m >> 7;
            int ks  = chb >> 3;
            int mt  = (m >> 4) & 7;
            int laneb = (m & 7) << 2;
            int reg = ((m >> 3) & 1) | (((chb >> 2) & 1) << 1);
            size_t base = ((((size_t)(mbk * 32 + ks) * 8 + mt) * 32 + laneb) * 4 + reg) * 2;
            float vv[4] = {v.x, v.y, v.z, v.w};
            #pragma unroll
            for (int e = 0; e < 4; e++) {
                float hi = tf32r(vv[e]);
                float lo = tf32r(vv[e] - hi);
                // lane = laneb + e  -> +e*8 floats
                *(float2*)&g_afrag[base + (size_t)e * 8] = make_float2(hi, lo);
            }
        }
        __syncthreads();
    }
}

// ---------------------------------------------------------------------------
// TF32 3-split warp-MMA GEMM, fused bias + GLU + residual.
//   CTA: 128 rows x (64 a-cols + 64 g-cols).  grid (256, 4).
//   8 warps: wm=wid&3 (m 32-row strip), wn=wid>>2 (8-ntile strip).
//   K pipelined in 8 chunks of 32 via cp.async double buffer.
// smem: 32768 floats = 128KB.  stage s at s*16384 floats (A 8192 | B 8192).
// Epilogue zbuf overlays smem with stride 132.
// ---------------------------------------------------------------------------
__global__ __launch_bounds__(256, 1) void gemm_glu_tc(
        const float* __restrict__ bias_all, int layer) {
    extern __shared__ float sm[];
    int tid = threadIdx.x, lane = tid & 31, wid = tid >> 5;
    int wm = wid & 3, wn = wid >> 2;
    int mb = blockIdx.x, nb = blockIdx.y;
    uint32_t sbase = smem_u32(sm);

    const float* Asrc = g_afrag + (size_t)mb * 65536;
    const float* Bsrc = g_wfrag + ((size_t)layer * 4 + nb) * 65536;

    float acc[2][8][4] = {};

    // prefetch stages 0, 1
    #pragma unroll
    for (int st = 0; st < 2; st++) {
        const float* as = Asrc + st * 8192;
        const float* bs = Bsrc + st * 8192;
        uint32_t da = sbase + st * 65536u;
        uint32_t db = da + 32768u;
        #pragma unroll
        for (int i = 0; i < 8; i++) {
            int idx = tid + i * 256;
            cp16(da + idx * 16, as + idx * 4);
            cp16(db + idx * 16, bs + idx * 4);
        }
        asm volatile("cp.async.commit_group;");
    }

    for (int kc = 0; kc < 8; kc++) {
        if (kc < 7) asm volatile("cp.async.wait_group 1;");
        else        asm volatile("cp.async.wait_group 0;");
        __syncthreads();
        const float* stA = sm + (kc & 1) * 16384;
        const float* stB = stA + 8192;
        #pragma unroll
        for (int ks = 0; ks < 4; ks++) {
            uint32_t ah[2][4], al[2][4];
            #pragma unroll
            for (int mt = 0; mt < 2; mt++) {
                const float* ap = &stA[ks * 2048 + (wm * 2 + mt) * 256 + lane * 8];
                float4 q0 = *(const float4*)ap;
                float4 q1 = *(const float4*)(ap + 4);
                ah[mt][0] = __float_as_uint(q0.x); al[mt][0] = __float_as_uint(q0.y);
                ah[mt][1] = __float_as_uint(q0.z); al[mt][1] = __float_as_uint(q0.w);
                ah[mt][2] = __float_as_uint(q1.x); al[mt][2] = __float_as_uint(q1.y);
                ah[mt][3] = __float_as_uint(q1.z); al[mt][3] = __float_as_uint(q1.w);
            }
            #pragma unroll
            for (int nt = 0; nt < 8; nt++) {
                float4 bq = *(const float4*)&stB[ks * 2048 + (wn * 8 + nt) * 128 + lane * 4];
                uint32_t bh0 = __float_as_uint(bq.x), bl0 = __float_as_uint(bq.y);
                uint32_t bh1 = __float_as_uint(bq.z), bl1 = __float_as_uint(bq.w);
                #pragma unroll
                for (int mt = 0; mt < 2; mt++) {
                    mma_tf32(acc[mt][nt], ah[mt], bh0, bh1);
                    mma_tf32(acc[mt][nt], al[mt], bh0, bh1);
                    mma_tf32(acc[mt][nt], ah[mt], bl0, bl1);
                }
            }
        }
        __syncthreads();
        if (kc < 6) {
            int st = kc + 2;
            const float* as = Asrc + st * 8192;
            const float* bs = Bsrc + st * 8192;
            uint32_t da = sbase + (kc & 1) * 65536u;
            uint32_t db = da + 32768u;
            #pragma unroll
            for (int i = 0; i < 8; i++) {
                int idx = tid + i * 256;
                cp16(da + idx * 16, as + idx * 4);
                cp16(db + idx * 16, bs + idx * 4);
            }
            asm volatile("cp.async.commit_group;");
        }
    }

    // epilogue: acc -> zbuf (stride 132), then GLU + residual -> g_zr
    #pragma unroll
    for (int mt = 0; mt < 2; mt++) {
        #pragma unroll
        for (int nt = 0; nt < 8; nt++) {
            int r0  = wm * 32 + mt * 16 + (lane >> 2);
            int col = (wn * 8 + nt) * 8 + (lane & 3) * 2;
            *(float2*)&sm[r0 * 132 + col]       = make_float2(acc[mt][nt][0], acc[mt][nt][1]);
            *(float2*)&sm[(r0 + 8) * 132 + col] = make_float2(acc[mt][nt][2], acc[mt][nt][3]);
        }
    }
    __syncthreads();

    int j  = tid & 63;
    int rb = tid >> 6;
    float ba = bias_all[layer * 512 + nb * 64 + j];
    float bg = bias_all[layer * 512 + 256 + nb * 64 + j];
    #pragma unroll 4
    for (int r = rb; r < 128; r += 4) {
        float a = sm[r * 132 + j] + ba;
        float gg = sm[r * 132 + 64 + j] + bg;
        float z = a / (1.0f + expf(-gg));
        size_t m = (size_t)mb * 128 + r;
        int n = nb * 64 + j;
        g_zr[m * HH + n] = z + g_h[m * HH + n];
    }
}

// ---------------------------------------------------------------------------
// LayerNorm over H=256: g_h = LN(g_zr)*gamma + beta.  One warp per row.
// ---------------------------------------------------------------------------
__global__ __launch_bounds__(256) void ln_kernel(
        const float* __restrict__ lng, const float* __restrict__ lnb, int layer) {
    int row  = blockIdx.x * 8 + (threadIdx.x >> 5);
    int lane = threadIdx.x & 31;
    const float* Z = g_zr + (size_t)row * HH;
    float4 v0 = *(const float4*)&Z[lane * 4];
    float4 v1 = *(const float4*)&Z[128 + lane * 4];
    float s  = v0.x + v0.y + v0.z + v0.w + v1.x + v1.y + v1.z + v1.w;
    float ss = v0.x*v0.x + v0.y*v0.y + v0.z*v0.z + v0.w*v0.w
             + v1.x*v1.x + v1.y*v1.y + v1.z*v1.z + v1.w*v1.w;
    #pragma unroll
    for (int o = 16; o; o >>= 1) {
        s  += __shfl_xor_sync(0xffffffffu, s,  o);
        ss += __shfl_xor_sync(0xffffffffu, ss, o);
    }
    float mean = s * (1.0f / 256.0f);
    float var  = ss * (1.0f / 256.0f) - mean * mean;
    float rstd = rsqrtf(var + 1e-5f);
    float* O = g_h + (size_t)row * HH;
    const float* G0 = &lng[layer * HH];
    const float* B0 = &lnb[layer * HH];
    float4 ga = *(const float4*)&G0[lane * 4];
    float4 gb = *(const float4*)&G0[128 + lane * 4];
    float4 ba = *(const float4*)&B0[lane * 4];
    float4 bb = *(const float4*)&B0[128 + lane * 4];
    float4 o0, o1;
    o0.x = (v0.x - mean) * rstd * ga.x + ba.x;
    o0.y = (v0.y - mean) * rstd * ga.y + ba.y;
    o0.z = (v0.z - mean) * rstd * ga.z + ba.z;
    o0.w = (v0.w - mean) * rstd * ga.w + ba.w;
    o1.x = (v1.x - mean) * rstd * gb.x + bb.x;
    o1.y = (v1.y - mean) * rstd * gb.y + bb.y;
    o1.z = (v1.z - mean) * rstd * gb.z + bb.z;
    o1.w = (v1.w - mean) * rstd * gb.w + bb.w;
    *(float4*)&O[lane * 4] = o0;
    *(float4*)&O[128 + lane * 4] = o1;
}

// ---------------------------------------------------------------------------
// Mean pool over L
// ---------------------------------------------------------------------------
__global__ __launch_bounds__(256) void pool_kernel() {
    int b = blockIdx.x, ch = threadIdx.x;
    const float* Hp = g_h + (size_t)b * LL * HH + ch;
    float s0 = 0.f, s1 = 0.f, s2 = 0.f, s3 = 0.f;
    for (int l = 0; l < LL; l += 4) {
        s0 += Hp[(size_t)(l + 0) * HH];
        s1 += Hp[(size_t)(l + 1) * HH];
        s2 += Hp[(size_t)(l + 2) * HH];
        s3 += Hp[(size_t)(l + 3) * HH];
    }
    g_pool[b * HH + ch] = (s0 + s1 + s2 + s3) * (1.0f / LL);
}

// ---------------------------------------------------------------------------
// Decoder MLP: 256 -> 128 relu -> 64 relu -> 32
// ---------------------------------------------------------------------------
__global__ __launch_bounds__(128) void decoder_kernel(
        const float* __restrict__ w1, const float* __restrict__ b1,
        const float* __restrict__ w2, const float* __restrict__ b2,
        const float* __restrict__ w3, const float* __restrict__ b3,
        float* __restrict__ out) {
    __shared__ float p[HH];
    __shared__ float q1[DM1];
    __shared__ float q2[DM2];
    int b = blockIdx.x, tid = threadIdx.x;
    p[tid]       = g_pool[b * HH + tid];
    p[tid + 128] = g_pool[b * HH + tid + 128];
    __syncthreads();
    {
        float s = b1[tid];
        #pragma unroll 4
        for (int k = 0; k < HH; k++) s = fmaf(p[k], w1[k * DM1 + tid], s);
        q1[tid] = fmaxf(s, 0.0f);
    }
    __syncthreads();
    if (tid < DM2) {
        float s = b2[tid];
        #pragma unroll 4
        for (int k = 0; k < DM1; k++) s = fmaf(q1[k], w2[k * DM2 + tid], s);
        q2[tid] = fmaxf(s, 0.0f);
    }
    __syncthreads();
    if (tid < DOUT) {
        float s = b3[tid];
        #pragma unroll 4
        for (int k = 0; k < DM2; k++) s = fmaf(q2[k], w3[k * DOUT + tid], s);
        out[b * DOUT + tid] = s;
    }
}

// ---------------------------------------------------------------------------
extern "C" void kernel_launch(void* const* d_in, const int* in_sizes, int n_in,
                              void* d_out, int out_size) {
    const float* x          = (const float*)d_in[0];
    const float* enc_w      = (const float*)d_in[1];
    const float* enc_b      = (const float*)d_in[2];
    const float* log_dt     = (const float*)d_in[3];
    const float* C_re       = (const float*)d_in[4];
    const float* C_im       = (const float*)d_in[5];
    const float* log_A_real = (const float*)d_in[6];
    const float* A_imag     = (const float*)d_in[7];
    const float* D_skip     = (const float*)d_in[8];
    const float* w_out      = (const float*)d_in[9];
    const float* b_out      = (const float*)d_in[10];
    const float* ln_g       = (const float*)d_in[11];
    const float* ln_b       = (const float*)d_in[12];
    const float* dec_w1     = (const float*)d_in[13];
    const float* dec_b1     = (const float*)d_in[14];
    const float* dec_w2     = (const float*)d_in[15];
    const float* dec_b2     = (const float*)d_in[16];
    const float* dec_w3     = (const float*)d_in[17];
    const float* dec_b3     = (const float*)d_in[18];
    float* out = (float*)d_out;

    cudaFuncSetAttribute(gemm_glu_tc,
                         cudaFuncAttributeMaxDynamicSharedMemorySize, 131072);

    prep_w_kernel<<<(NLAYERS * 512 * HH + 255) / 256, 256>>>(w_out);
    dim3 enc_grid(MROWS / 64, HH / 64);
    encoder_kernel<<<enc_grid, 256>>>(x, enc_w, enc_b);
    for (int layer = 0; layer < NLAYERS; layer++) {
        scan_kernel<<<dim3(BB, HH / 16), 128>>>(log_dt, C_re, C_im,
                                                log_A_real, A_imag, D_skip, layer);
        gemm_glu_tc<<<dim3(NMBLK, 4), 256, 131072>>>(b_out, layer);
        ln_kernel<<<MROWS / 8, 256>>>(ln_g, ln_b, layer);
    }
    pool_kernel<<<BB, 256>>>();
    decoder_kernel<<<BB, 128>>>(dec_w1, dec_b1, dec_w2, dec_b2, dec_w3, dec_b3, out);
}

// round 5
// speedup vs baseline: 1.4769x; 1.4769x over previous
#include <cuda_runtime.h>
#include <cuda_bf16.h>
#include <cstdint>
#include <math.h>

#define BB 16
#define LL 2048
#define DIN 64
#define HH 256
#define NH 32
#define NLAYERS 4
#define DM1 128
#define DM2 64
#define DOUT 32

#define MROWS (BB*LL)          // 32768
#define NMBLK (MROWS/128)      // 256 row blocks

// Scratch (allocation-free contract: __device__ globals)
__device__ float g_h  [MROWS*HH];                // hidden state (B*L, H)
__device__ float g_zr [MROWS*HH];                // glu + residual (pre-LN)
// A fragments (bf16 pairs): [mblock(256)][kchunk(8)][ks(2)][mtile(8)][reg(4)][lane(32)]
__device__ __align__(16) uint32_t g_af_hi[(size_t)NMBLK*16384];
__device__ __align__(16) uint32_t g_af_lo[(size_t)NMBLK*16384];
// B fragments (bf16 pairs): [layer][nb(4)][kchunk(8)][ks(2)][nt(16)][lane(32)][reg(2)]
__device__ __align__(16) uint32_t g_wf_hi[(size_t)NLAYERS*4*16384];
__device__ __align__(16) uint32_t g_wf_lo[(size_t)NLAYERS*4*16384];
__device__ float g_pool[BB*HH];

// ---------------------------------------------------------------------------
// helpers
// ---------------------------------------------------------------------------
__device__ __forceinline__ uint32_t smem_u32(const void* p) {
    uint32_t a;
    asm("{ .reg .u64 t; cvta.to.shared.u64 t, %1; cvt.u32.u64 %0, t; }"
        : "=r"(a) : "l"(p));
    return a;
}
__device__ __forceinline__ unsigned short bfu(float x) {
    return __bfloat16_as_ushort(__float2bfloat16_rn(x));
}
__device__ __forceinline__ float bff(unsigned short u) {
    return __bfloat162float(__ushort_as_bfloat16(u));
}
__device__ __forceinline__ void cp16(uint32_t dst, const void* src) {
    asm volatile("cp.async.cg.shared.global [%0], [%1], 16;"
                 :: "r"(dst), "l"(src));
}
__device__ __forceinline__ void mma_bf16(float* d, const uint32_t* a,
                                         uint32_t b0, uint32_t b1) {
    asm volatile(
        "mma.sync.aligned.m16n8k16.row.col.f32.bf16.bf16.f32 "
        "{%0,%1,%2,%3}, {%4,%5,%6,%7}, {%8,%9}, {%0,%1,%2,%3};"
        : "+f"(d[0]), "+f"(d[1]), "+f"(d[2]), "+f"(d[3])
        : "r"(a[0]), "r"(a[1]), "r"(a[2]), "r"(a[3]), "r"(b0), "r"(b1));
}

// ---------------------------------------------------------------------------
// Weight prep: bf16x3 split of w_out into fragment-ordered g_wf_hi/lo.
// w layout [layer][o(512)][h(256)]; thread handles one (layer, o, h-pair).
// ---------------------------------------------------------------------------
__global__ __launch_bounds__(256) void prep_w_kernel(const float* __restrict__ w) {
    int i = blockIdx.x * 256 + threadIdx.x;
    if (i >= NLAYERS * 512 * 128) return;
    int hp = i & 127;          int h = hp * 2;
    int o  = (i >> 7) & 511;
    int layer = i >> 16;
    float v0 = w[((size_t)(layer * 512) + o) * 256 + h];
    float v1 = w[((size_t)(layer * 512) + o) * 256 + h + 1];
    unsigned short h0 = bfu(v0), h1 = bfu(v1);
    unsigned short l0 = bfu(v0 - bff(h0)), l1 = bfu(v1 - bff(h1));
    int half = o >> 8;
    int nb   = (o & 255) >> 6;
    int nt   = ((o >> 3) & 7) | (half << 3);
    int gid  = o & 7;
    int kchunk = h >> 5;
    int ks   = (h >> 4) & 1;
    int kk   = h & 15;
    int tig  = (kk & 7) >> 1;
    int reg  = kk >> 3;
    int lane = gid * 4 + tig;
    size_t idx = (((((size_t)(layer * 4 + nb) * 8 + kchunk) * 2 + ks) * 16 + nt) * 32 + lane) * 2 + reg;
    g_wf_hi[idx] = (uint32_t)h0 | ((uint32_t)h1 << 16);
    g_wf_lo[idx] = (uint32_t)l0 | ((uint32_t)l1 << 16);
}

// ---------------------------------------------------------------------------
// Encoder: g_h[m, n] = x[m, :64] @ enc_w[:, n] + enc_b[n]  (fp32 SIMT, small)
// ---------------------------------------------------------------------------
__global__ __launch_bounds__(256) void encoder_kernel(
        const float* __restrict__ X, const float* __restrict__ W,
        const float* __restrict__ bias) {
    __shared__ float As[64][36];
    __shared__ float Bs[32][68];
    int row0 = blockIdx.x * 64;
    int n0   = blockIdx.y * 64;
    int tid = threadIdx.x;
    int tx = tid & 15, ty = tid >> 4;
    float acc[4][4] = {};
    for (int k0 = 0; k0 < DIN; k0 += 32) {
        #pragma unroll
        for (int p = 0; p < 2; p++) {
            int q = tid + p * 256;
            int r = q >> 3, kq = q & 7;
            float4 v = *(const float4*)&X[(row0 + r) * DIN + k0 + kq * 4];
            *(float4*)&As[r][kq * 4] = v;
        }
        #pragma unroll
        for (int p = 0; p < 2; p++) {
            int q = tid + p * 256;
            int kk = q >> 4, nq = q & 15;
            float4 v = *(const float4*)&W[(k0 + kk) * HH + n0 + nq * 4];
            *(float4*)&Bs[kk][nq * 4] = v;
        }
        __syncthreads();
        #pragma unroll
        for (int k = 0; k < 32; k++) {
            float a[4];
            #pragma unroll
            for (int i = 0; i < 4; i++) a[i] = As[ty * 4 + i][k];
            float4 bv = *(const float4*)&Bs[k][tx * 4];
            float bj[4] = {bv.x, bv.y, bv.z, bv.w};
            #pragma unroll
            for (int i = 0; i < 4; i++)
                #pragma unroll
                for (int j = 0; j < 4; j++)
                    acc[i][j] = fmaf(a[i], bj[j], acc[i][j]);
        }
        __syncthreads();
    }
    #pragma unroll
    for (int i = 0; i < 4; i++) {
        int m = row0 + ty * 4 + i;
        #pragma unroll
        for (int j = 0; j < 4; j++) {
            int n = n0 + tx * 4 + j;
            g_h[m * HH + n] = acc[i][j] + bias[n];
        }
    }
}

// ---------------------------------------------------------------------------
// S4D scan fused with D-skip + exact GELU; emits bf16x3 fragment pairs.
// ---------------------------------------------------------------------------
#define SCAN_T 128
__global__ __launch_bounds__(128) void scan_kernel(
        const float* __restrict__ log_dt, const float* __restrict__ C_re,
        const float* __restrict__ C_im,   const float* __restrict__ log_A_real,
        const float* __restrict__ A_imag, const float* __restrict__ D_skip,
        int layer) {
    __shared__ float s_in [SCAN_T * 16];
    __shared__ float s_out[SCAN_T * 16];
    int b   = blockIdx.x;
    int ch0 = blockIdx.y * 16;
    int tid = threadIdx.x;
    int warp = tid >> 5, lane = tid & 31;
    int g = lane >> 3, j = lane & 7;
    int c_local = warp * 4 + g;
    int ch = ch0 + c_local;

    float dt  = expf(log_dt[layer * HH + ch]);
    float dsk = D_skip[layer * HH + ch];
    float w_re[4], w_im[4], ck_re[4], ck_im[4], s_re[4], s_im[4];
    #pragma unroll
    for (int k = 0; k < 4; k++) {
        int n = j * 4 + k;
        int idx = (layer * HH + ch) * NH + n;
        float Are = -expf(log_A_real[idx]);
        float Aim = A_imag[idx];
        float er  = expf(dt * Are);
        float wre = er * cosf(dt * Aim);
        float wim = er * sinf(dt * Aim);
        w_re[k] = wre; w_im[k] = wim;
        float nre = wre - 1.0f, nim = wim;
        float inv = 1.0f / (Are * Are + Aim * Aim);
        float ire = Are * inv, iim = -Aim * inv;
        float tre = nre * ire - nim * iim;
        float tim = nre * iim + nim * ire;
        float cre = C_re[idx], cim = C_im[idx];
        ck_re[k] = 2.0f * (cre * tre - cim * tim);
        ck_im[k] = 2.0f * (cre * tim + cim * tre);
        s_re[k] = 0.0f; s_im[k] = 0.0f;
    }

    const float* hin = g_h + (size_t)b * LL * HH;

    for (int l0 = 0; l0 < LL; l0 += SCAN_T) {
        #pragma unroll
        for (int p = 0; p < 4; p++) {
            int q = tid + p * 128;
            int t = q >> 2, cq = q & 3;
            float4 v = *(const float4*)&hin[(l0 + t) * HH + ch0 + cq * 4];
            *(float4*)&s_in[t * 16 + cq * 4] = v;
        }
        __syncthreads();
        #pragma unroll 4
        for (int t = 0; t < SCAN_T; t++) {
            float u = s_in[t * 16 + c_local];
            float pacc = 0.0f;
            #pragma unroll
            for (int k = 0; k < 4; k++) {
                float nr = fmaf(w_re[k], s_re[k], u);
                nr = fmaf(-w_im[k], s_im[k], nr);
                float ni = w_re[k] * s_im[k];
                ni = fmaf(w_im[k], s_re[k], ni);
                s_re[k] = nr; s_im[k] = ni;
                pacc = fmaf(ck_re[k], nr, pacc);
                pacc = fmaf(-ck_im[k], ni, pacc);
            }
            pacc += __shfl_xor_sync(0xffffffffu, pacc, 1);
            pacc += __shfl_xor_sync(0xffffffffu, pacc, 2);
            pacc += __shfl_xor_sync(0xffffffffu, pacc, 4);
            if (j == 0)
                s_out[t * 16 + c_local] = fmaf(u, dsk, pacc);
        }
        __syncthreads();
        #pragma unroll
        for (int p = 0; p < 4; p++) {
            int q = tid + p * 128;
            int t = q >> 2, cq = q & 3;
            float4 v = *(const float4*)&s_out[t * 16 + cq * 4];
            v.x = 0.5f * v.x * (1.0f + erff(v.x * 0.70710678118654752f));
            v.y = 0.5f * v.y * (1.0f + erff(v.y * 0.70710678118654752f));
            v.z = 0.5f * v.z * (1.0f + erff(v.z * 0.70710678118654752f));
            v.w = 0.5f * v.w * (1.0f + erff(v.w * 0.70710678118654752f));
            int m   = b * LL + l0 + t;
            int chb = ch0 + cq * 4;
            int mblk   = m >> 7;
            int mtile  = (m >> 4) & 7;
            int rowsel = (m >> 3) & 1;
            int gid    = m & 7;
            int kchunk = chb >> 5;
            int ks     = (chb >> 4) & 1;
            int kk     = chb & 15;
            int reg    = rowsel + ((kk >> 3) << 1);
            int tig    = (kk & 7) >> 1;
            int lane2  = gid * 4 + tig;
            size_t idx = (size_t)mblk * 16384 +
                         ((((kchunk * 2 + ks) * 8 + mtile) * 4 + reg) * 32 + lane2);
            unsigned short hx = bfu(v.x), hy = bfu(v.y), hz = bfu(v.z), hw = bfu(v.w);
            unsigned short lx = bfu(v.x - bff(hx)), ly = bfu(v.y - bff(hy));
            unsigned short lz = bfu(v.z - bff(hz)), lw = bfu(v.w - bff(hw));
            uint2 hi2, lo2;
            hi2.x = (uint32_t)hx | ((uint32_t)hy << 16);
            hi2.y = (uint32_t)hz | ((uint32_t)hw << 16);
            lo2.x = (uint32_t)lx | ((uint32_t)ly << 16);
            lo2.y = (uint32_t)lz | ((uint32_t)lw << 16);
            *(uint2*)&g_af_hi[idx] = hi2;
            *(uint2*)&g_af_lo[idx] = lo2;
        }
        __syncthreads();
    }
}

// ---------------------------------------------------------------------------
// bf16x3 warp-MMA GEMM, fused bias + GLU + residual.
//   CTA: 128 rows x (64 a-cols + 64 g-cols).  grid (256, 4).
//   8 warps: wm=wid&3 (32-row strip), wn=wid>>2 (8-ntile strip).
//   K in 8 chunks of 32, cp.async double buffer (32KB/stage, 64KB total).
// Epilogue zbuf overlays smem (128 x 132 floats = 67584 B).
// ---------------------------------------------------------------------------
#define GEMM_SMEM 67584
__global__ __launch_bounds__(256, 2) void gemm_glu_tc(
        const float* __restrict__ bias_all, int layer) {
    extern __shared__ uint32_t sm[];
    float* smf = (float*)sm;
    int tid = threadIdx.x, lane = tid & 31, wid = tid >> 5;
    int wm = wid & 3, wn = wid >> 2;
    int mb = blockIdx.x, nb = blockIdx.y;
    uint32_t sbase = smem_u32(sm);

    const uint32_t* Ah = g_af_hi + (size_t)mb * 16384;
    const uint32_t* Al = g_af_lo + (size_t)mb * 16384;
    const uint32_t* Bh = g_wf_hi + (size_t)(layer * 4 + nb) * 16384;
    const uint32_t* Bl = g_wf_lo + (size_t)(layer * 4 + nb) * 16384;

    float acc[2][8][4] = {};

    // prefetch stages 0, 1 (each stage: Ah 2048 | Al 2048 | Bh 2048 | Bl 2048 u32)
    #pragma unroll
    for (int st = 0; st < 2; st++) {
        uint32_t db = sbase + st * 32768u;
        #pragma unroll
        for (int ii = 0; ii < 2; ii++) {
            int c = tid + ii * 256;                    // 512 chunks of 16B per array
            cp16(db +          c * 16, Ah + (size_t)st * 2048 + c * 4);
            cp16(db +  8192u + c * 16, Al + (size_t)st * 2048 + c * 4);
            cp16(db + 16384u + c * 16, Bh + (size_t)st * 2048 + c * 4);
            cp16(db + 24576u + c * 16, Bl + (size_t)st * 2048 + c * 4);
        }
        asm volatile("cp.async.commit_group;");
    }

    for (int kc = 0; kc < 8; kc++) {
        if (kc < 7) asm volatile("cp.async.wait_group 1;");
        else        asm volatile("cp.async.wait_group 0;");
        __syncthreads();
        const uint32_t* sAh = sm + (kc & 1) * 8192;
        const uint32_t* sAl = sAh + 2048;
        const uint32_t* sBh = sAh + 4096;
        const uint32_t* sBl = sAh + 6144;
        #pragma unroll
        for (int ks = 0; ks < 2; ks++) {
            uint32_t ah[2][4], al[2][4];
            #pragma unroll
            for (int mt = 0; mt < 2; mt++) {
                int base = (ks * 8 + wm * 2 + mt) * 128 + lane;
                #pragma unroll
                for (int r = 0; r < 4; r++) {
                    ah[mt][r] = sAh[base + r * 32];
                    al[mt][r] = sAl[base + r * 32];
                }
            }
            #pragma unroll
            for (int nt = 0; nt < 8; nt++) {
                int bidx = ((ks * 16 + wn * 8 + nt) * 32 + lane) * 2;
                uint2 bh = *(const uint2*)&sBh[bidx];
                uint2 bl = *(const uint2*)&sBl[bidx];
                #pragma unroll
                for (int mt = 0; mt < 2; mt++) {
                    mma_bf16(acc[mt][nt], ah[mt], bh.x, bh.y);
                    mma_bf16(acc[mt][nt], al[mt], bh.x, bh.y);
                    mma_bf16(acc[mt][nt], ah[mt], bl.x, bl.y);
                }
            }
        }
        __syncthreads();
        if (kc < 6) {
            int st = kc + 2;
            uint32_t db = sbase + (kc & 1) * 32768u;
            #pragma unroll
            for (int ii = 0; ii < 2; ii++) {
                int c = tid + ii * 256;
                cp16(db +          c * 16, Ah + (size_t)st * 2048 + c * 4);
                cp16(db +  8192u + c * 16, Al + (size_t)st * 2048 + c * 4);
                cp16(db + 16384u + c * 16, Bh + (size_t)st * 2048 + c * 4);
                cp16(db + 24576u + c * 16, Bl + (size_t)st * 2048 + c * 4);
            }
            asm volatile("cp.async.commit_group;");
        }
    }

    // epilogue: acc -> zbuf (stride 132), then GLU + residual -> g_zr
    #pragma unroll
    for (int mt = 0; mt < 2; mt++) {
        #pragma unroll
        for (int nt = 0; nt < 8; nt++) {
            int r0  = wm * 32 + mt * 16 + (lane >> 2);
            int col = (wn * 8 + nt) * 8 + (lane & 3) * 2;
            *(float2*)&smf[r0 * 132 + col]       = make_float2(acc[mt][nt][0], acc[mt][nt][1]);
            *(float2*)&smf[(r0 + 8) * 132 + col] = make_float2(acc[mt][nt][2], acc[mt][nt][3]);
        }
    }
    __syncthreads();

    int j  = tid & 63;
    int rb = tid >> 6;
    float ba = bias_all[layer * 512 + nb * 64 + j];
    float bg = bias_all[layer * 512 + 256 + nb * 64 + j];
    #pragma unroll 4
    for (int r = rb; r < 128; r += 4) {
        float a  = smf[r * 132 + j] + ba;
        float gg = smf[r * 132 + 64 + j] + bg;
        float z = a / (1.0f + expf(-gg));
        size_t m = (size_t)mb * 128 + r;
        int n = nb * 64 + j;
        g_zr[m * HH + n] = z + g_h[m * HH + n];
    }
}

// ---------------------------------------------------------------------------
// LayerNorm over H=256: g_h = LN(g_zr)*gamma + beta.  One warp per row.
// ---------------------------------------------------------------------------
__global__ __launch_bounds__(256) void ln_kernel(
        const float* __restrict__ lng, const float* __restrict__ lnb, int layer) {
    int row  = blockIdx.x * 8 + (threadIdx.x >> 5);
    int lane = threadIdx.x & 31;
    const float* Z = g_zr + (size_t)row * HH;
    float4 v0 = *(const float4*)&Z[lane * 4];
    float4 v1 = *(const float4*)&Z[128 + lane * 4];
    float s  = v0.x + v0.y + v0.z + v0.w + v1.x + v1.y + v1.z + v1.w;
    float ss = v0.x*v0.x + v0.y*v0.y + v0.z*v0.z + v0.w*v0.w
             + v1.x*v1.x + v1.y*v1.y + v1.z*v1.z + v1.w*v1.w;
    #pragma unroll
    for (int o = 16; o; o >>= 1) {
        s  += __shfl_xor_sync(0xffffffffu, s,  o);
        ss += __shfl_xor_sync(0xffffffffu, ss, o);
    }
    float mean = s * (1.0f / 256.0f);
    float var  = ss * (1.0f / 256.0f) - mean * mean;
    float rstd = rsqrtf(var + 1e-5f);
    float* O = g_h + (size_t)row * HH;
    const float* G0 = &lng[layer * HH];
    const float* B0 = &lnb[layer * HH];
    float4 ga = *(const float4*)&G0[lane * 4];
    float4 gb = *(const float4*)&G0[128 + lane * 4];
    float4 ba = *(const float4*)&B0[lane * 4];
    float4 bb = *(const float4*)&B0[128 + lane * 4];
    float4 o0, o1;
    o0.x = (v0.x - mean) * rstd * ga.x + ba.x;
    o0.y = (v0.y - mean) * rstd * ga.y + ba.y;
    o0.z = (v0.z - mean) * rstd * ga.z + ba.z;
    o0.w = (v0.w - mean) * rstd * ga.w + ba.w;
    o1.x = (v1.x - mean) * rstd * gb.x + bb.x;
    o1.y = (v1.y - mean) * rstd * gb.y + bb.y;
    o1.z = (v1.z - mean) * rstd * gb.z + bb.z;
    o1.w = (v1.w - mean) * rstd * gb.w + bb.w;
    *(float4*)&O[lane * 4] = o0;
    *(float4*)&O[128 + lane * 4] = o1;
}

// ---------------------------------------------------------------------------
// Mean pool over L
// ---------------------------------------------------------------------------
__global__ __launch_bounds__(256) void pool_kernel() {
    int b = blockIdx.x, ch = threadIdx.x;
    const float* Hp = g_h + (size_t)b * LL * HH + ch;
    float s0 = 0.f, s1 = 0.f, s2 = 0.f, s3 = 0.f;
    for (int l = 0; l < LL; l += 4) {
        s0 += Hp[(size_t)(l + 0) * HH];
        s1 += Hp[(size_t)(l + 1) * HH];
        s2 += Hp[(size_t)(l + 2) * HH];
        s3 += Hp[(size_t)(l + 3) * HH];
    }
    g_pool[b * HH + ch] = (s0 + s1 + s2 + s3) * (1.0f / LL);
}

// ---------------------------------------------------------------------------
// Decoder MLP: 256 -> 128 relu -> 64 relu -> 32
// ---------------------------------------------------------------------------
__global__ __launch_bounds__(128) void decoder_kernel(
        const float* __restrict__ w1, const float* __restrict__ b1,
        const float* __restrict__ w2, const float* __restrict__ b2,
        const float* __restrict__ w3, const float* __restrict__ b3,
        float* __restrict__ out) {
    __shared__ float p[HH];
    __shared__ float q1[DM1];
    __shared__ float q2[DM2];
    int b = blockIdx.x, tid = threadIdx.x;
    p[tid]       = g_pool[b * HH + tid];
    p[tid + 128] = g_pool[b * HH + tid + 128];
    __syncthreads();
    {
        float s = b1[tid];
        #pragma unroll 4
        for (int k = 0; k < HH; k++) s = fmaf(p[k], w1[k * DM1 + tid], s);
        q1[tid] = fmaxf(s, 0.0f);
    }
    __syncthreads();
    if (tid < DM2) {
        float s = b2[tid];
        #pragma unroll 4
        for (int k = 0; k < DM1; k++) s = fmaf(q1[k], w2[k * DM2 + tid], s);
        q2[tid] = fmaxf(s, 0.0f);
    }
    __syncthreads();
    if (tid < DOUT) {
        float s = b3[tid];
        #pragma unroll 4
        for (int k = 0; k < DM2; k++) s = fmaf(q2[k], w3[k * DOUT + tid], s);
        out[b * DOUT + tid] = s;
    }
}

// ---------------------------------------------------------------------------
extern "C" void kernel_launch(void* const* d_in, const int* in_sizes, int n_in,
                              void* d_out, int out_size) {
    const float* x          = (const float*)d_in[0];
    const float* enc_w      = (const float*)d_in[1];
    const float* enc_b      = (const float*)d_in[2];
    const float* log_dt     = (const float*)d_in[3];
    const float* C_re       = (const float*)d_in[4];
    const float* C_im       = (const float*)d_in[5];
    const float* log_A_real = (const float*)d_in[6];
    const float* A_imag     = (const float*)d_in[7];
    const float* D_skip     = (const float*)d_in[8];
    const float* w_out      = (const float*)d_in[9];
    const float* b_out      = (const float*)d_in[10];
    const float* ln_g       = (const float*)d_in[11];
    const float* ln_b       = (const float*)d_in[12];
    const float* dec_w1     = (const float*)d_in[13];
    const float* dec_b1     = (const float*)d_in[14];
    const float* dec_w2     = (const float*)d_in[15];
    const float* dec_b2     = (const float*)d_in[16];
    const float* dec_w3     = (const float*)d_in[17];
    const float* dec_b3     = (const float*)d_in[18];
    float* out = (float*)d_out;

    cudaFuncSetAttribute(gemm_glu_tc,
                         cudaFuncAttributeMaxDynamicSharedMemorySize, GEMM_SMEM);

    prep_w_kernel<<<(NLAYERS * 512 * 128 + 255) / 256, 256>>>(w_out);
    dim3 enc_grid(MROWS / 64, HH / 64);
    encoder_kernel<<<enc_grid, 256>>>(x, enc_w, enc_b);
    for (int layer = 0; layer < NLAYERS; layer++) {
        scan_kernel<<<dim3(BB, HH / 16), 128>>>(log_dt, C_re, C_im,
                                                log_A_real, A_imag, D_skip, layer);
        gemm_glu_tc<<<dim3(NMBLK, 4), 256, GEMM_SMEM>>>(b_out, layer);
        ln_kernel<<<MROWS / 8, 256>>>(ln_g, ln_b, layer);
    }
    pool_kernel<<<BB, 256>>>();
    decoder_kernel<<<BB, 128>>>(dec_w1, dec_b1, dec_w2, dec_b2, dec_w3, dec_b3, out);
}

// round 6
// speedup vs baseline: 1.7706x; 1.1989x over previous
#include <cuda_runtime.h>
#include <cuda_bf16.h>
#include <cstdint>
#include <math.h>

#define BB 16
#define LL 2048
#define DIN 64
#define HH 256
#define NH 32
#define NLAYERS 4
#define DM1 128
#define DM2 64
#define DOUT 32

#define MROWS (BB*LL)          // 32768
#define NMBLK (MROWS/128)      // 256 row blocks

#define NCHUNK 8
#define CLEN (LL/NCHUNK)       // 256

// Scratch (allocation-free contract: __device__ globals)
__device__ float g_h  [MROWS*HH];                // hidden state (B*L, H)
__device__ float g_zr [MROWS*HH];                // glu + residual (pre-LN)
// A fragments (bf16 pairs): [mblock(256)][kchunk(8)][ks(2)][mtile(8)][reg(4)][lane(32)]
__device__ __align__(16) uint32_t g_af_hi[(size_t)NMBLK*16384];
__device__ __align__(16) uint32_t g_af_lo[(size_t)NMBLK*16384];
// B fragments (bf16 pairs): [layer][nb(4)][kchunk(8)][ks(2)][nt(16)][lane(32)][reg(2)]
__device__ __align__(16) uint32_t g_wf_hi[(size_t)NLAYERS*4*16384];
__device__ __align__(16) uint32_t g_wf_lo[(size_t)NLAYERS*4*16384];
// scan carries: [chunk][b][ch][state] complex
__device__ float2 g_carry[(size_t)NCHUNK*BB*HH*NH];
__device__ float g_pool[BB*HH];

// ---------------------------------------------------------------------------
// helpers
// ---------------------------------------------------------------------------
__device__ __forceinline__ uint32_t smem_u32(const void* p) {
    uint32_t a;
    asm("{ .reg .u64 t; cvta.to.shared.u64 t, %1; cvt.u32.u64 %0, t; }"
        : "=r"(a) : "l"(p));
    return a;
}
__device__ __forceinline__ unsigned short bfu(float x) {
    return __bfloat16_as_ushort(__float2bfloat16_rn(x));
}
__device__ __forceinline__ float bff(unsigned short u) {
    return __bfloat162float(__ushort_as_bfloat16(u));
}
__device__ __forceinline__ void cp16(uint32_t dst, const void* src) {
    asm volatile("cp.async.cg.shared.global [%0], [%1], 16;"
                 :: "r"(dst), "l"(src));
}
__device__ __forceinline__ void mma_bf16(float* d, const uint32_t* a,
                                         uint32_t b0, uint32_t b1) {
    asm volatile(
        "mma.sync.aligned.m16n8k16.row.col.f32.bf16.bf16.f32 "
        "{%0,%1,%2,%3}, {%4,%5,%6,%7}, {%8,%9}, {%0,%1,%2,%3};"
        : "+f"(d[0]), "+f"(d[1]), "+f"(d[2]), "+f"(d[3])
        : "r"(a[0]), "r"(a[1]), "r"(a[2]), "r"(a[3]), "r"(b0), "r"(b1));
}

// ---------------------------------------------------------------------------
// Weight prep: bf16x3 split of w_out into fragment-ordered g_wf_hi/lo.
// ---------------------------------------------------------------------------
__global__ __launch_bounds__(256) void prep_w_kernel(const float* __restrict__ w) {
    int i = blockIdx.x * 256 + threadIdx.x;
    if (i >= NLAYERS * 512 * 128) return;
    int hp = i & 127;          int h = hp * 2;
    int o  = (i >> 7) & 511;
    int layer = i >> 16;
    float v0 = w[((size_t)(layer * 512) + o) * 256 + h];
    float v1 = w[((size_t)(layer * 512) + o) * 256 + h + 1];
    unsigned short h0 = bfu(v0), h1 = bfu(v1);
    unsigned short l0 = bfu(v0 - bff(h0)), l1 = bfu(v1 - bff(h1));
    int half = o >> 8;
    int nb   = (o & 255) >> 6;
    int nt   = ((o >> 3) & 7) | (half << 3);
    int gid  = o & 7;
    int kchunk = h >> 5;
    int ks   = (h >> 4) & 1;
    int kk   = h & 15;
    int tig  = (kk & 7) >> 1;
    int reg  = kk >> 3;
    int lane = gid * 4 + tig;
    size_t idx = (((((size_t)(layer * 4 + nb) * 8 + kchunk) * 2 + ks) * 16 + nt) * 32 + lane) * 2 + reg;
    g_wf_hi[idx] = (uint32_t)h0 | ((uint32_t)h1 << 16);
    g_wf_lo[idx] = (uint32_t)l0 | ((uint32_t)l1 << 16);
}

// ---------------------------------------------------------------------------
// Encoder: g_h[m, n] = x[m, :64] @ enc_w[:, n] + enc_b[n]  (fp32 SIMT, small)
// ---------------------------------------------------------------------------
__global__ __launch_bounds__(256) void encoder_kernel(
        const float* __restrict__ X, const float* __restrict__ W,
        const float* __restrict__ bias) {
    __shared__ float As[64][36];
    __shared__ float Bs[32][68];
    int row0 = blockIdx.x * 64;
    int n0   = blockIdx.y * 64;
    int tid = threadIdx.x;
    int tx = tid & 15, ty = tid >> 4;
    float acc[4][4] = {};
    for (int k0 = 0; k0 < DIN; k0 += 32) {
        #pragma unroll
        for (int p = 0; p < 2; p++) {
            int q = tid + p * 256;
            int r = q >> 3, kq = q & 7;
            float4 v = *(const float4*)&X[(row0 + r) * DIN + k0 + kq * 4];
            *(float4*)&As[r][kq * 4] = v;
        }
        #pragma unroll
        for (int p = 0; p < 2; p++) {
            int q = tid + p * 256;
            int kk = q >> 4, nq = q & 15;
            float4 v = *(const float4*)&W[(k0 + kk) * HH + n0 + nq * 4];
            *(float4*)&Bs[kk][nq * 4] = v;
        }
        __syncthreads();
        #pragma unroll
        for (int k = 0; k < 32; k++) {
            float a[4];
            #pragma unroll
            for (int i = 0; i < 4; i++) a[i] = As[ty * 4 + i][k];
            float4 bv = *(const float4*)&Bs[k][tx * 4];
            float bj[4] = {bv.x, bv.y, bv.z, bv.w};
            #pragma unroll
            for (int i = 0; i < 4; i++)
                #pragma unroll
                for (int j = 0; j < 4; j++)
                    acc[i][j] = fmaf(a[i], bj[j], acc[i][j]);
        }
        __syncthreads();
    }
    #pragma unroll
    for (int i = 0; i < 4; i++) {
        int m = row0 + ty * 4 + i;
        #pragma unroll
        for (int j = 0; j < 4; j++) {
            int n = n0 + tx * 4 + j;
            g_h[m * HH + n] = acc[i][j] + bias[n];
        }
    }
}

// ---------------------------------------------------------------------------
// Scan phase 1: per-chunk local recurrence from zero state; saves end state.
// grid (B, H/16, NCHUNK), block 128.  warp=4 channels, 8 lanes/ch, 4 states.
// ---------------------------------------------------------------------------
__global__ __launch_bounds__(128) void scan_p1(
        const float* __restrict__ log_dt, const float* __restrict__ log_A_real,
        const float* __restrict__ A_imag, int layer) {
    __shared__ float s_in[128 * 16];
    int b   = blockIdx.x;
    int ch0 = blockIdx.y * 16;
    int chunk = blockIdx.z;
    int tid = threadIdx.x;
    int warp = tid >> 5, lane = tid & 31;
    int g = lane >> 3, j = lane & 7;
    int c_local = warp * 4 + g;
    int ch = ch0 + c_local;

    float dt = expf(log_dt[layer * HH + ch]);
    float w_re[4], w_im[4], s_re[4], s_im[4];
    #pragma unroll
    for (int k = 0; k < 4; k++) {
        int n = j * 4 + k;
        int idx = (layer * HH + ch) * NH + n;
        float Are = -expf(log_A_real[idx]);
        float Aim = A_imag[idx];
        float er  = expf(dt * Are);
        w_re[k] = er * cosf(dt * Aim);
        w_im[k] = er * sinf(dt * Aim);
        s_re[k] = 0.0f; s_im[k] = 0.0f;
    }

    const float* hin = g_h + (size_t)b * LL * HH + (size_t)chunk * CLEN * HH;
    for (int l0 = 0; l0 < CLEN; l0 += 128) {
        #pragma unroll
        for (int p = 0; p < 4; p++) {
            int q = tid + p * 128;
            int t = q >> 2, cq = q & 3;
            float4 v = *(const float4*)&hin[(l0 + t) * HH + ch0 + cq * 4];
            *(float4*)&s_in[t * 16 + cq * 4] = v;
        }
        __syncthreads();
        #pragma unroll 8
        for (int t = 0; t < 128; t++) {
            float u = s_in[t * 16 + c_local];
            #pragma unroll
            for (int k = 0; k < 4; k++) {
                float nr = fmaf(w_re[k], s_re[k], u);
                nr = fmaf(-w_im[k], s_im[k], nr);
                float ni = w_re[k] * s_im[k];
                ni = fmaf(w_im[k], s_re[k], ni);
                s_re[k] = nr; s_im[k] = ni;
            }
        }
        __syncthreads();
    }
    // write end state
    size_t cbase = ((size_t)(chunk * BB + b) * HH + ch) * NH + j * 4;
    #pragma unroll
    for (int k = 0; k < 4; k++)
        g_carry[cbase + k] = make_float2(s_re[k], s_im[k]);
}

// ---------------------------------------------------------------------------
// Scan combine: sequentially propagate carries across chunks.
// thread = (b, ch, n).  g_carry[c] becomes the TRUE state at chunk c start.
// ---------------------------------------------------------------------------
__global__ __launch_bounds__(256) void scan_comb(
        const float* __restrict__ log_dt, const float* __restrict__ log_A_real,
        const float* __restrict__ A_imag, int layer) {
    int gi = blockIdx.x * 256 + threadIdx.x;     // (b*HH + ch)*NH + n
    int n  = gi & 31;
    int ch = (gi >> 5) & 255;
    float dt = expf(log_dt[layer * HH + ch]);
    int idxp = (layer * HH + ch) * NH + n;
    float Are = -expf(log_A_real[idxp]);
    float Aim = A_imag[idxp];
    float er  = expf((float)CLEN * dt * Are);
    float ang = (float)CLEN * dt * Aim;
    float wp_re = er * cosf(ang);
    float wp_im = er * sinf(ang);
    float cs_re = 0.0f, cs_im = 0.0f;
    #pragma unroll
    for (int c = 0; c < NCHUNK; c++) {
        size_t idx = (size_t)c * (BB * HH * NH) + gi;
        float2 se = g_carry[idx];
        g_carry[idx] = make_float2(cs_re, cs_im);
        float nr = wp_re * cs_re - wp_im * cs_im + se.x;
        float ni = wp_re * cs_im + wp_im * cs_re + se.y;
        cs_re = nr; cs_im = ni;
    }
}

// ---------------------------------------------------------------------------
// Scan phase 2: per-chunk scan from true carry; fused D-skip + GELU +
// bf16x3 fragment emission.  grid (B, H/16, NCHUNK), block 128.
// ---------------------------------------------------------------------------
__global__ __launch_bounds__(128) void scan_p2(
        const float* __restrict__ log_dt, const float* __restrict__ C_re,
        const float* __restrict__ C_im,   const float* __restrict__ log_A_real,
        const float* __restrict__ A_imag, const float* __restrict__ D_skip,
        int layer) {
    __shared__ float s_in [128 * 16];
    __shared__ float s_out[128 * 16];
    int b   = blockIdx.x;
    int ch0 = blockIdx.y * 16;
    int chunk = blockIdx.z;
    int tid = threadIdx.x;
    int warp = tid >> 5, lane = tid & 31;
    int g = lane >> 3, j = lane & 7;
    int c_local = warp * 4 + g;
    int ch = ch0 + c_local;

    float dt  = expf(log_dt[layer * HH + ch]);
    float dsk = D_skip[layer * HH + ch];
    float w_re[4], w_im[4], ck_re[4], ck_im[4], s_re[4], s_im[4];
    size_t cbase = ((size_t)(chunk * BB + b) * HH + ch) * NH + j * 4;
    #pragma unroll
    for (int k = 0; k < 4; k++) {
        int n = j * 4 + k;
        int idx = (layer * HH + ch) * NH + n;
        float Are = -expf(log_A_real[idx]);
        float Aim = A_imag[idx];
        float er  = expf(dt * Are);
        float wre = er * cosf(dt * Aim);
        float wim = er * sinf(dt * Aim);
        w_re[k] = wre; w_im[k] = wim;
        float nre = wre - 1.0f, nim = wim;
        float inv = 1.0f / (Are * Are + Aim * Aim);
        float ire = Are * inv, iim = -Aim * inv;
        float tre = nre * ire - nim * iim;
        float tim = nre * iim + nim * ire;
        float cre = C_re[idx], cim = C_im[idx];
        ck_re[k] = 2.0f * (cre * tre - cim * tim);
        ck_im[k] = 2.0f * (cre * tim + cim * tre);
        float2 cs = g_carry[cbase + k];
        s_re[k] = cs.x; s_im[k] = cs.y;
    }

    const float* hin = g_h + (size_t)b * LL * HH + (size_t)chunk * CLEN * HH;

    for (int l0 = 0; l0 < CLEN; l0 += 128) {
        #pragma unroll
        for (int p = 0; p < 4; p++) {
            int q = tid + p * 128;
            int t = q >> 2, cq = q & 3;
            float4 v = *(const float4*)&hin[(l0 + t) * HH + ch0 + cq * 4];
            *(float4*)&s_in[t * 16 + cq * 4] = v;
        }
        __syncthreads();
        #pragma unroll 4
        for (int t = 0; t < 128; t++) {
            float u = s_in[t * 16 + c_local];
            float pacc = 0.0f;
            #pragma unroll
            for (int k = 0; k < 4; k++) {
                float nr = fmaf(w_re[k], s_re[k], u);
                nr = fmaf(-w_im[k], s_im[k], nr);
                float ni = w_re[k] * s_im[k];
                ni = fmaf(w_im[k], s_re[k], ni);
                s_re[k] = nr; s_im[k] = ni;
                pacc = fmaf(ck_re[k], nr, pacc);
                pacc = fmaf(-ck_im[k], ni, pacc);
            }
            pacc += __shfl_xor_sync(0xffffffffu, pacc, 1);
            pacc += __shfl_xor_sync(0xffffffffu, pacc, 2);
            pacc += __shfl_xor_sync(0xffffffffu, pacc, 4);
            if (j == 0)
                s_out[t * 16 + c_local] = fmaf(u, dsk, pacc);
        }
        __syncthreads();
        #pragma unroll
        for (int p = 0; p < 4; p++) {
            int q = tid + p * 128;
            int t = q >> 2, cq = q & 3;
            float4 v = *(const float4*)&s_out[t * 16 + cq * 4];
            v.x = 0.5f * v.x * (1.0f + erff(v.x * 0.70710678118654752f));
            v.y = 0.5f * v.y * (1.0f + erff(v.y * 0.70710678118654752f));
            v.z = 0.5f * v.z * (1.0f + erff(v.z * 0.70710678118654752f));
            v.w = 0.5f * v.w * (1.0f + erff(v.w * 0.70710678118654752f));
            int m   = b * LL + chunk * CLEN + l0 + t;
            int chb = ch0 + cq * 4;
            int mblk   = m >> 7;
            int mtile  = (m >> 4) & 7;
            int rowsel = (m >> 3) & 1;
            int gid    = m & 7;
            int kchunk = chb >> 5;
            int ks     = (chb >> 4) & 1;
            int kk     = chb & 15;
            int reg    = rowsel + ((kk >> 3) << 1);
            int tig    = (kk & 7) >> 1;
            int lane2  = gid * 4 + tig;
            size_t idx = (size_t)mblk * 16384 +
                         ((((kchunk * 2 + ks) * 8 + mtile) * 4 + reg) * 32 + lane2);
            unsigned short hx = bfu(v.x), hy = bfu(v.y), hz = bfu(v.z), hw = bfu(v.w);
            unsigned short lx = bfu(v.x - bff(hx)), ly = bfu(v.y - bff(hy));
            unsigned short lz = bfu(v.z - bff(hz)), lw = bfu(v.w - bff(hw));
            uint2 hi2, lo2;
            hi2.x = (uint32_t)hx | ((uint32_t)hy << 16);
            hi2.y = (uint32_t)hz | ((uint32_t)hw << 16);
            lo2.x = (uint32_t)lx | ((uint32_t)ly << 16);
            lo2.y = (uint32_t)lz | ((uint32_t)lw << 16);
            *(uint2*)&g_af_hi[idx] = hi2;
            *(uint2*)&g_af_lo[idx] = lo2;
        }
        __syncthreads();
    }
}

// ---------------------------------------------------------------------------
// bf16x3 warp-MMA GEMM, fused bias + GLU + residual.  (unchanged from R5)
// ---------------------------------------------------------------------------
#define GEMM_SMEM 67584
__global__ __launch_bounds__(256, 2) void gemm_glu_tc(
        const float* __restrict__ bias_all, int layer) {
    extern __shared__ uint32_t sm[];
    float* smf = (float*)sm;
    int tid = threadIdx.x, lane = tid & 31, wid = tid >> 5;
    int wm = wid & 3, wn = wid >> 2;
    int mb = blockIdx.x, nb = blockIdx.y;
    uint32_t sbase = smem_u32(sm);

    const uint32_t* Ah = g_af_hi + (size_t)mb * 16384;
    const uint32_t* Al = g_af_lo + (size_t)mb * 16384;
    const uint32_t* Bh = g_wf_hi + (size_t)(layer * 4 + nb) * 16384;
    const uint32_t* Bl = g_wf_lo + (size_t)(layer * 4 + nb) * 16384;

    float acc[2][8][4] = {};

    #pragma unroll
    for (int st = 0; st < 2; st++) {
        uint32_t db = sbase + st * 32768u;
        #pragma unroll
        for (int ii = 0; ii < 2; ii++) {
            int c = tid + ii * 256;
            cp16(db +          c * 16, Ah + (size_t)st * 2048 + c * 4);
            cp16(db +  8192u + c * 16, Al + (size_t)st * 2048 + c * 4);
            cp16(db + 16384u + c * 16, Bh + (size_t)st * 2048 + c * 4);
            cp16(db + 24576u + c * 16, Bl + (size_t)st * 2048 + c * 4);
        }
        asm volatile("cp.async.commit_group;");
    }

    for (int kc = 0; kc < 8; kc++) {
        if (kc < 7) asm volatile("cp.async.wait_group 1;");
        else        asm volatile("cp.async.wait_group 0;");
        __syncthreads();
        const uint32_t* sAh = sm + (kc & 1) * 8192;
        const uint32_t* sAl = sAh + 2048;
        const uint32_t* sBh = sAh + 4096;
        const uint32_t* sBl = sAh + 6144;
        #pragma unroll
        for (int ks = 0; ks < 2; ks++) {
            uint32_t ah[2][4], al[2][4];
            #pragma unroll
            for (int mt = 0; mt < 2; mt++) {
                int base = (ks * 8 + wm * 2 + mt) * 128 + lane;
                #pragma unroll
                for (int r = 0; r < 4; r++) {
                    ah[mt][r] = sAh[base + r * 32];
                    al[mt][r] = sAl[base + r * 32];
                }
            }
            #pragma unroll
            for (int nt = 0; nt < 8; nt++) {
                int bidx = ((ks * 16 + wn * 8 + nt) * 32 + lane) * 2;
                uint2 bh = *(const uint2*)&sBh[bidx];
                uint2 bl = *(const uint2*)&sBl[bidx];
                #pragma unroll
                for (int mt = 0; mt < 2; mt++) {
                    mma_bf16(acc[mt][nt], ah[mt], bh.x, bh.y);
                    mma_bf16(acc[mt][nt], al[mt], bh.x, bh.y);
                    mma_bf16(acc[mt][nt], ah[mt], bl.x, bl.y);
                }
            }
        }
        __syncthreads();
        if (kc < 6) {
            int st = kc + 2;
            uint32_t db = sbase + (kc & 1) * 32768u;
            #pragma unroll
            for (int ii = 0; ii < 2; ii++) {
                int c = tid + ii * 256;
                cp16(db +          c * 16, Ah + (size_t)st * 2048 + c * 4);
                cp16(db +  8192u + c * 16, Al + (size_t)st * 2048 + c * 4);
                cp16(db + 16384u + c * 16, Bh + (size_t)st * 2048 + c * 4);
                cp16(db + 24576u + c * 16, Bl + (size_t)st * 2048 + c * 4);
            }
            asm volatile("cp.async.commit_group;");
        }
    }

    #pragma unroll
    for (int mt = 0; mt < 2; mt++) {
        #pragma unroll
        for (int nt = 0; nt < 8; nt++) {
            int r0  = wm * 32 + mt * 16 + (lane >> 2);
            int col = (wn * 8 + nt) * 8 + (lane & 3) * 2;
            *(float2*)&smf[r0 * 132 + col]       = make_float2(acc[mt][nt][0], acc[mt][nt][1]);
            *(float2*)&smf[(r0 + 8) * 132 + col] = make_float2(acc[mt][nt][2], acc[mt][nt][3]);
        }
    }
    __syncthreads();

    int j  = tid & 63;
    int rb = tid >> 6;
    float ba = bias_all[layer * 512 + nb * 64 + j];
    float bg = bias_all[layer * 512 + 256 + nb * 64 + j];
    #pragma unroll 4
    for (int r = rb; r < 128; r += 4) {
        float a  = smf[r * 132 + j] + ba;
        float gg = smf[r * 132 + 64 + j] + bg;
        float z = a / (1.0f + expf(-gg));
        size_t m = (size_t)mb * 128 + r;
        int n = nb * 64 + j;
        g_zr[m * HH + n] = z + g_h[m * HH + n];
    }
}

// ---------------------------------------------------------------------------
// LayerNorm over H=256: g_h = LN(g_zr)*gamma + beta.  One warp per row.
// ---------------------------------------------------------------------------
__global__ __launch_bounds__(256) void ln_kernel(
        const float* __restrict__ lng, const float* __restrict__ lnb, int layer) {
    int row  = blockIdx.x * 8 + (threadIdx.x >> 5);
    int lane = threadIdx.x & 31;
    const float* Z = g_zr + (size_t)row * HH;
    float4 v0 = *(const float4*)&Z[lane * 4];
    float4 v1 = *(const float4*)&Z[128 + lane * 4];
    float s  = v0.x + v0.y + v0.z + v0.w + v1.x + v1.y + v1.z + v1.w;
    float ss = v0.x*v0.x + v0.y*v0.y + v0.z*v0.z + v0.w*v0.w
             + v1.x*v1.x + v1.y*v1.y + v1.z*v1.z + v1.w*v1.w;
    #pragma unroll
    for (int o = 16; o; o >>= 1) {
        s  += __shfl_xor_sync(0xffffffffu, s,  o);
        ss += __shfl_xor_sync(0xffffffffu, ss, o);
    }
    float mean = s * (1.0f / 256.0f);
    float var  = ss * (1.0f / 256.0f) - mean * mean;
    float rstd = rsqrtf(var + 1e-5f);
    float* O = g_h + (size_t)row * HH;
    const float* G0 = &lng[layer * HH];
    const float* B0 = &lnb[layer * HH];
    float4 ga = *(const float4*)&G0[lane * 4];
    float4 gb = *(const float4*)&G0[128 + lane * 4];
    float4 ba = *(const float4*)&B0[lane * 4];
    float4 bb = *(const float4*)&B0[128 + lane * 4];
    float4 o0, o1;
    o0.x = (v0.x - mean) * rstd * ga.x + ba.x;
    o0.y = (v0.y - mean) * rstd * ga.y + ba.y;
    o0.z = (v0.z - mean) * rstd * ga.z + ba.z;
    o0.w = (v0.w - mean) * rstd * ga.w + ba.w;
    o1.x = (v1.x - mean) * rstd * gb.x + bb.x;
    o1.y = (v1.y - mean) * rstd * gb.y + bb.y;
    o1.z = (v1.z - mean) * rstd * gb.z + bb.z;
    o1.w = (v1.w - mean) * rstd * gb.w + bb.w;
    *(float4*)&O[lane * 4] = o0;
    *(float4*)&O[128 + lane * 4] = o1;
}

// ---------------------------------------------------------------------------
// Mean pool over L
// ---------------------------------------------------------------------------
__global__ __launch_bounds__(256) void pool_kernel() {
    int b = blockIdx.x, ch = threadIdx.x;
    const float* Hp = g_h + (size_t)b * LL * HH + ch;
    float s0 = 0.f, s1 = 0.f, s2 = 0.f, s3 = 0.f;
    for (int l = 0; l < LL; l += 4) {
        s0 += Hp[(size_t)(l + 0) * HH];
        s1 += Hp[(size_t)(l + 1) * HH];
        s2 += Hp[(size_t)(l + 2) * HH];
        s3 += Hp[(size_t)(l + 3) * HH];
    }
    g_pool[b * HH + ch] = (s0 + s1 + s2 + s3) * (1.0f / LL);
}

// ---------------------------------------------------------------------------
// Decoder MLP: 256 -> 128 relu -> 64 relu -> 32
// ---------------------------------------------------------------------------
__global__ __launch_bounds__(128) void decoder_kernel(
        const float* __restrict__ w1, const float* __restrict__ b1,
        const float* __restrict__ w2, const float* __restrict__ b2,
        const float* __restrict__ w3, const float* __restrict__ b3,
        float* __restrict__ out) {
    __shared__ float p[HH];
    __shared__ float q1[DM1];
    __shared__ float q2[DM2];
    int b = blockIdx.x, tid = threadIdx.x;
    p[tid]       = g_pool[b * HH + tid];
    p[tid + 128] = g_pool[b * HH + tid + 128];
    __syncthreads();
    {
        float s = b1[tid];
        #pragma unroll 4
        for (int k = 0; k < HH; k++) s = fmaf(p[k], w1[k * DM1 + tid], s);
        q1[tid] = fmaxf(s, 0.0f);
    }
    __syncthreads();
    if (tid < DM2) {
        float s = b2[tid];
        #pragma unroll 4
        for (int k = 0; k < DM1; k++) s = fmaf(q1[k], w2[k * DM2 + tid], s);
        q2[tid] = fmaxf(s, 0.0f);
    }
    __syncthreads();
    if (tid < DOUT) {
        float s = b3[tid];
        #pragma unroll 4
        for (int k = 0; k < DM2; k++) s = fmaf(q2[k], w3[k * DOUT + tid], s);
        out[b * DOUT + tid] = s;
    }
}

// ---------------------------------------------------------------------------
extern "C" void kernel_launch(void* const* d_in, const int* in_sizes, int n_in,
                              void* d_out, int out_size) {
    const float* x          = (const float*)d_in[0];
    const float* enc_w      = (const float*)d_in[1];
    const float* enc_b      = (const float*)d_in[2];
    const float* log_dt     = (const float*)d_in[3];
    const float* C_re       = (const float*)d_in[4];
    const float* C_im       = (const float*)d_in[5];
    const float* log_A_real = (const float*)d_in[6];
    const float* A_imag     = (const float*)d_in[7];
    const float* D_skip     = (const float*)d_in[8];
    const float* w_out      = (const float*)d_in[9];
    const float* b_out      = (const float*)d_in[10];
    const float* ln_g       = (const float*)d_in[11];
    const float* ln_b       = (const float*)d_in[12];
    const float* dec_w1     = (const float*)d_in[13];
    const float* dec_b1     = (const float*)d_in[14];
    const float* dec_w2     = (const float*)d_in[15];
    const float* dec_b2     = (const float*)d_in[16];
    const float* dec_w3     = (const float*)d_in[17];
    const float* dec_b3     = (const float*)d_in[18];
    float* out = (float*)d_out;

    cudaFuncSetAttribute(gemm_glu_tc,
                         cudaFuncAttributeMaxDynamicSharedMemorySize, GEMM_SMEM);

    prep_w_kernel<<<(NLAYERS * 512 * 128 + 255) / 256, 256>>>(w_out);
    dim3 enc_grid(MROWS / 64, HH / 64);
    encoder_kernel<<<enc_grid, 256>>>(x, enc_w, enc_b);
    dim3 scan_grid(BB, HH / 16, NCHUNK);
    for (int layer = 0; layer < NLAYERS; layer++) {
        scan_p1<<<scan_grid, 128>>>(log_dt, log_A_real, A_imag, layer);
        scan_comb<<<BB * HH * NH / 256, 256>>>(log_dt, log_A_real, A_imag, layer);
        scan_p2<<<scan_grid, 128>>>(log_dt, C_re, C_im,
                                    log_A_real, A_imag, D_skip, layer);
        gemm_glu_tc<<<dim3(NMBLK, 4), 256, GEMM_SMEM>>>(b_out, layer);
        ln_kernel<<<MROWS / 8, 256>>>(ln_g, ln_b, layer);
    }
    pool_kernel<<<BB, 256>>>();
    decoder_kernel<<<BB, 128>>>(dec_w1, dec_b1, dec_w2, dec_b2, dec_w3, dec_b3, out);
}

// round 8
// speedup vs baseline: 1.9095x; 1.0784x over previous
#include <cuda_runtime.h>
#include <cuda_bf16.h>
#include <cstdint>
#include <math.h>

#define BB 16
#define LL 2048
#define DIN 64
#define HH 256
#define NH 32
#define NLAYERS 4
#define DM1 128
#define DM2 64
#define DOUT 32

#define MROWS (BB*LL)          // 32768
#define NMBLK (MROWS/128)      // 256 row blocks

#define NCHUNK 16
#define CLEN (LL/NCHUNK)       // 128

// Scratch (allocation-free contract: __device__ globals)
__device__ float g_h  [MROWS*HH];                // hidden state (B*L, H)
__device__ float g_zr [MROWS*HH];                // glu + residual (pre-LN)
// A fragments (bf16 pairs): [mblock(256)][kchunk(8)][ks(2)][mtile(8)][reg(4)][lane(32)]
__device__ __align__(16) uint32_t g_af_hi[(size_t)NMBLK*16384];
__device__ __align__(16) uint32_t g_af_lo[(size_t)NMBLK*16384];
// B fragments (bf16 pairs): [layer][nb(4)][kchunk(8)][ks(2)][nt(16)][lane(32)][reg(2)]
__device__ __align__(16) uint32_t g_wf_hi[(size_t)NLAYERS*4*16384];
__device__ __align__(16) uint32_t g_wf_lo[(size_t)NLAYERS*4*16384];
// scan carries: [chunk][b][ch][state] complex
__device__ float2 g_carry[(size_t)NCHUNK*BB*HH*NH];
__device__ float g_pool[BB*HH];

// ---------------------------------------------------------------------------
// helpers
// ---------------------------------------------------------------------------
__device__ __forceinline__ uint32_t smem_u32(const void* p) {
    uint32_t a;
    asm("{ .reg .u64 t; cvta.to.shared.u64 t, %1; cvt.u32.u64 %0, t; }"
        : "=r"(a) : "l"(p));
    return a;
}
__device__ __forceinline__ unsigned short bfu(float x) {
    return __bfloat16_as_ushort(__float2bfloat16_rn(x));
}
__device__ __forceinline__ float bff(unsigned short u) {
    return __bfloat162float(__ushort_as_bfloat16(u));
}
__device__ __forceinline__ void cp16(uint32_t dst, const void* src) {
    asm volatile("cp.async.cg.shared.global [%0], [%1], 16;"
                 :: "r"(dst), "l"(src));
}
__device__ __forceinline__ void mma_bf16(float* d, const uint32_t* a,
                                         uint32_t b0, uint32_t b1) {
    asm volatile(
        "mma.sync.aligned.m16n8k16.row.col.f32.bf16.bf16.f32 "
        "{%0,%1,%2,%3}, {%4,%5,%6,%7}, {%8,%9}, {%0,%1,%2,%3};"
        : "+f"(d[0]), "+f"(d[1]), "+f"(d[2]), "+f"(d[3])
        : "r"(a[0]), "r"(a[1]), "r"(a[2]), "r"(a[3]), "r"(b0), "r"(b1));
}

// ---------------------------------------------------------------------------
// Weight prep: bf16x3 split of w_out into fragment-ordered g_wf_hi/lo.
// ---------------------------------------------------------------------------
__global__ __launch_bounds__(256) void prep_w_kernel(const float* __restrict__ w) {
    int i = blockIdx.x * 256 + threadIdx.x;
    if (i >= NLAYERS * 512 * 128) return;
    int hp = i & 127;          int h = hp * 2;
    int o  = (i >> 7) & 511;
    int layer = i >> 16;
    float v0 = w[((size_t)(layer * 512) + o) * 256 + h];
    float v1 = w[((size_t)(layer * 512) + o) * 256 + h + 1];
    unsigned short h0 = bfu(v0), h1 = bfu(v1);
    unsigned short l0 = bfu(v0 - bff(h0)), l1 = bfu(v1 - bff(h1));
    int half = o >> 8;
    int nb   = (o & 255) >> 6;
    int nt   = ((o >> 3) & 7) | (half << 3);
    int gid  = o & 7;
    int kchunk = h >> 5;
    int ks   = (h >> 4) & 1;
    int kk   = h & 15;
    int tig  = (kk & 7) >> 1;
    int reg  = kk >> 3;
    int lane = gid * 4 + tig;
    size_t idx = (((((size_t)(layer * 4 + nb) * 8 + kchunk) * 2 + ks) * 16 + nt) * 32 + lane) * 2 + reg;
    g_wf_hi[idx] = (uint32_t)h0 | ((uint32_t)h1 << 16);
    g_wf_lo[idx] = (uint32_t)l0 | ((uint32_t)l1 << 16);
}

// ---------------------------------------------------------------------------
// Encoder: g_h[m, n] = x[m, :64] @ enc_w[:, n] + enc_b[n]  (fp32 SIMT, small)
// ---------------------------------------------------------------------------
__global__ __launch_bounds__(256) void encoder_kernel(
        const float* __restrict__ X, const float* __restrict__ W,
        const float* __restrict__ bias) {
    __shared__ float As[64][36];
    __shared__ float Bs[32][68];
    int row0 = blockIdx.x * 64;
    int n0   = blockIdx.y * 64;
    int tid = threadIdx.x;
    int tx = tid & 15, ty = tid >> 4;
    float acc[4][4] = {};
    for (int k0 = 0; k0 < DIN; k0 += 32) {
        #pragma unroll
        for (int p = 0; p < 2; p++) {
            int q = tid + p * 256;
            int r = q >> 3, kq = q & 7;
            float4 v = *(const float4*)&X[(row0 + r) * DIN + k0 + kq * 4];
            *(float4*)&As[r][kq * 4] = v;
        }
        #pragma unroll
        for (int p = 0; p < 2; p++) {
            int q = tid + p * 256;
            int kk = q >> 4, nq = q & 15;
            float4 v = *(const float4*)&W[(k0 + kk) * HH + n0 + nq * 4];
            *(float4*)&Bs[kk][nq * 4] = v;
        }
        __syncthreads();
        #pragma unroll
        for (int k = 0; k < 32; k++) {
            float a[4];
            #pragma unroll
            for (int i = 0; i < 4; i++) a[i] = As[ty * 4 + i][k];
            float4 bv = *(const float4*)&Bs[k][tx * 4];
            float bj[4] = {bv.x, bv.y, bv.z, bv.w};
            #pragma unroll
            for (int i = 0; i < 4; i++)
                #pragma unroll
                for (int j = 0; j < 4; j++)
                    acc[i][j] = fmaf(a[i], bj[j], acc[i][j]);
        }
        __syncthreads();
    }
    #pragma unroll
    for (int i = 0; i < 4; i++) {
        int m = row0 + ty * 4 + i;
        #pragma unroll
        for (int j = 0; j < 4; j++) {
            int n = n0 + tx * 4 + j;
            g_h[m * HH + n] = acc[i][j] + bias[n];
        }
    }
}

// ---------------------------------------------------------------------------
// Scan phase 1: per-chunk local recurrence from zero state; saves end state.
// grid (B, H/16, NCHUNK-1), block 128.  (last chunk's end state is unused)
// ---------------------------------------------------------------------------
__global__ __launch_bounds__(128) void scan_p1(
        const float* __restrict__ log_dt, const float* __restrict__ log_A_real,
        const float* __restrict__ A_imag, int layer) {
    __shared__ float s_in[128 * 16];
    int b   = blockIdx.x;
    int ch0 = blockIdx.y * 16;
    int chunk = blockIdx.z;
    int tid = threadIdx.x;
    int warp = tid >> 5, lane = tid & 31;
    int g = lane >> 3, j = lane & 7;
    int c_local = warp * 4 + g;
    int ch = ch0 + c_local;

    float dt = expf(log_dt[layer * HH + ch]);
    float w_re[4], w_im[4], s_re[4], s_im[4];
    #pragma unroll
    for (int k = 0; k < 4; k++) {
        int n = j * 4 + k;
        int idx = (layer * HH + ch) * NH + n;
        float Are = -expf(log_A_real[idx]);
        float Aim = A_imag[idx];
        float er  = expf(dt * Are);
        w_re[k] = er * cosf(dt * Aim);
        w_im[k] = er * sinf(dt * Aim);
        s_re[k] = 0.0f; s_im[k] = 0.0f;
    }

    const float* hin = g_h + (size_t)b * LL * HH + (size_t)chunk * CLEN * HH;
    #pragma unroll
    for (int p = 0; p < 4; p++) {
        int q = tid + p * 128;
        int t = q >> 2, cq = q & 3;
        float4 v = *(const float4*)&hin[t * HH + ch0 + cq * 4];
        *(float4*)&s_in[t * 16 + cq * 4] = v;
    }
    __syncthreads();
    #pragma unroll 8
    for (int t = 0; t < CLEN; t++) {
        float u = s_in[t * 16 + c_local];
        #pragma unroll
        for (int k = 0; k < 4; k++) {
            float nr = fmaf(w_re[k], s_re[k], u);
            nr = fmaf(-w_im[k], s_im[k], nr);
            float ni = w_re[k] * s_im[k];
            ni = fmaf(w_im[k], s_re[k], ni);
            s_re[k] = nr; s_im[k] = ni;
        }
    }
    size_t cbase = ((size_t)(chunk * BB + b) * HH + ch) * NH + j * 4;
    #pragma unroll
    for (int k = 0; k < 4; k++)
        g_carry[cbase + k] = make_float2(s_re[k], s_im[k]);
}

// ---------------------------------------------------------------------------
// Scan combine: sequentially propagate carries across chunks.
// ---------------------------------------------------------------------------
__global__ __launch_bounds__(256) void scan_comb(
        const float* __restrict__ log_dt, const float* __restrict__ log_A_real,
        const float* __restrict__ A_imag, int layer) {
    int gi = blockIdx.x * 256 + threadIdx.x;     // (b*HH + ch)*NH + n
    int n  = gi & 31;
    int ch = (gi >> 5) & 255;
    float dt = expf(log_dt[layer * HH + ch]);
    int idxp = (layer * HH + ch) * NH + n;
    float Are = -expf(log_A_real[idxp]);
    float Aim = A_imag[idxp];
    float er  = expf((float)CLEN * dt * Are);
    float ang = (float)CLEN * dt * Aim;
    float wp_re = er * cosf(ang);
    float wp_im = er * sinf(ang);
    float cs_re = 0.0f, cs_im = 0.0f;
    #pragma unroll
    for (int c = 0; c < NCHUNK; c++) {
        size_t idx = (size_t)c * (BB * HH * NH) + gi;
        float2 se = g_carry[idx];
        g_carry[idx] = make_float2(cs_re, cs_im);
        float nr = wp_re * cs_re - wp_im * cs_im + se.x;
        float ni = wp_re * cs_im + wp_im * cs_re + se.y;
        cs_re = nr; cs_im = ni;
    }
}

// ---------------------------------------------------------------------------
// Scan phase 2: per-chunk scan from true carry; fused D-skip + GELU +
// bf16x3 fragment emission.  grid (B, H/16, NCHUNK), block 128.
// ---------------------------------------------------------------------------
__global__ __launch_bounds__(128) void scan_p2(
        const float* __restrict__ log_dt, const float* __restrict__ C_re,
        const float* __restrict__ C_im,   const float* __restrict__ log_A_real,
        const float* __restrict__ A_imag, const float* __restrict__ D_skip,
        int layer) {
    __shared__ float s_in [128 * 16];
    __shared__ float s_out[128 * 16];
    int b   = blockIdx.x;
    int ch0 = blockIdx.y * 16;
    int chunk = blockIdx.z;
    int tid = threadIdx.x;
    int warp = tid >> 5, lane = tid & 31;
    int g = lane >> 3, j = lane & 7;
    int c_local = warp * 4 + g;
    int ch = ch0 + c_local;

    float dt  = expf(log_dt[layer * HH + ch]);
    float dsk = D_skip[layer * HH + ch];
    float w_re[4], w_im[4], ck_re[4], ck_im[4], s_re[4], s_im[4];
    size_t cbase = ((size_t)(chunk * BB + b) * HH + ch) * NH + j * 4;
    #pragma unroll
    for (int k = 0; k < 4; k++) {
        int n = j * 4 + k;
        int idx = (layer * HH + ch) * NH + n;
        float Are = -expf(log_A_real[idx]);
        float Aim = A_imag[idx];
        float er  = expf(dt * Are);
        float wre = er * cosf(dt * Aim);
        float wim = er * sinf(dt * Aim);
        w_re[k] = wre; w_im[k] = wim;
        float nre = wre - 1.0f, nim = wim;
        float inv = 1.0f / (Are * Are + Aim * Aim);
        float ire = Are * inv, iim = -Aim * inv;
        float tre = nre * ire - nim * iim;
        float tim = nre * iim + nim * ire;
        float cre = C_re[idx], cim = C_im[idx];
        ck_re[k] = 2.0f * (cre * tre - cim * tim);
        ck_im[k] = 2.0f * (cre * tim + cim * tre);
        float2 cs = (chunk == 0) ? make_float2(0.0f, 0.0f) : g_carry[cbase + k];
        s_re[k] = cs.x; s_im[k] = cs.y;
    }

    const float* hin = g_h + (size_t)b * LL * HH + (size_t)chunk * CLEN * HH;

    #pragma unroll
    for (int p = 0; p < 4; p++) {
        int q = tid + p * 128;
        int t = q >> 2, cq = q & 3;
        float4 v = *(const float4*)&hin[t * HH + ch0 + cq * 4];
        *(float4*)&s_in[t * 16 + cq * 4] = v;
    }
    __syncthreads();
    #pragma unroll 4
    for (int t = 0; t < CLEN; t++) {
        float u = s_in[t * 16 + c_local];
        float pacc = 0.0f;
        #pragma unroll
        for (int k = 0; k < 4; k++) {
            float nr = fmaf(w_re[k], s_re[k], u);
            nr = fmaf(-w_im[k], s_im[k], nr);
            float ni = w_re[k] * s_im[k];
            ni = fmaf(w_im[k], s_re[k], ni);
            s_re[k] = nr; s_im[k] = ni;
            pacc = fmaf(ck_re[k], nr, pacc);
            pacc = fmaf(-ck_im[k], ni, pacc);
        }
        pacc += __shfl_xor_sync(0xffffffffu, pacc, 1);
        pacc += __shfl_xor_sync(0xffffffffu, pacc, 2);
        pacc += __shfl_xor_sync(0xffffffffu, pacc, 4);
        if (j == 0)
            s_out[t * 16 + c_local] = fmaf(u, dsk, pacc);
    }
    __syncthreads();
    #pragma unroll
    for (int p = 0; p < 4; p++) {
        int q = tid + p * 128;
        int t = q >> 2, cq = q & 3;
        float4 v = *(const float4*)&s_out[t * 16 + cq * 4];
        v.x = 0.5f * v.x * (1.0f + erff(v.x * 0.70710678118654752f));
        v.y = 0.5f * v.y * (1.0f + erff(v.y * 0.70710678118654752f));
        v.z = 0.5f * v.z * (1.0f + erff(v.z * 0.70710678118654752f));
        v.w = 0.5f * v.w * (1.0f + erff(v.w * 0.70710678118654752f));
        int m   = b * LL + chunk * CLEN + t;
        int chb = ch0 + cq * 4;
        int mblk   = m >> 7;
        int mtile  = (m >> 4) & 7;
        int rowsel = (m >> 3) & 1;
        int gid    = m & 7;
        int kchunk = chb >> 5;
        int ks     = (chb >> 4) & 1;
        int kk     = chb & 15;
        int reg    = rowsel + ((kk >> 3) << 1);
        int tig    = (kk & 7) >> 1;
        int lane2  = gid * 4 + tig;
        size_t idx = (size_t)mblk * 16384 +
                     ((((kchunk * 2 + ks) * 8 + mtile) * 4 + reg) * 32 + lane2);
        unsigned short hx = bfu(v.x), hy = bfu(v.y), hz = bfu(v.z), hw = bfu(v.w);
        unsigned short lx = bfu(v.x - bff(hx)), ly = bfu(v.y - bff(hy));
        unsigned short lz = bfu(v.z - bff(hz)), lw = bfu(v.w - bff(hw));
        uint2 hi2, lo2;
        hi2.x = (uint32_t)hx | ((uint32_t)hy << 16);
        hi2.y = (uint32_t)hz | ((uint32_t)hw << 16);
        lo2.x = (uint32_t)lx | ((uint32_t)ly << 16);
        lo2.y = (uint32_t)lz | ((uint32_t)lw << 16);
        *(uint2*)&g_af_hi[idx] = hi2;
        *(uint2*)&g_af_lo[idx] = lo2;
    }
}

// ---------------------------------------------------------------------------
// bf16x3 warp-MMA GEMM, register-GLU epilogue, 3-stage cp.async pipeline.
//   CTA: 128 rows x (64 a-cols + 64 g-cols paired).  grid (256, 4).
//   8 warps: wm=wid&3 (32-row strip), wn=wid>>2 (32-col group).
//   Warp wn owns a-ntiles {wn*4+i} and g-ntiles {8+wn*4+i} -> GLU in regs.
// smem: 3 stages x 32KB = 96KB.
// ---------------------------------------------------------------------------
#define GEMM_SMEM 98304
__global__ __launch_bounds__(256, 2) void gemm_glu_tc(
        const float* __restrict__ bias_all, int layer) {
    extern __shared__ uint32_t sm[];
    int tid = threadIdx.x, lane = tid & 31, wid = tid >> 5;
    int wm = wid & 3, wn = wid >> 2;
    int mb = blockIdx.x, nb = blockIdx.y;
    uint32_t sbase = smem_u32(sm);

    const uint32_t* Ah = g_af_hi + (size_t)mb * 16384;
    const uint32_t* Al = g_af_lo + (size_t)mb * 16384;
    const uint32_t* Bh = g_wf_hi + (size_t)(layer * 4 + nb) * 16384;
    const uint32_t* Bl = g_wf_lo + (size_t)(layer * 4 + nb) * 16384;

    float acca[2][4][4] = {};     // a-half accumulators
    float accg[2][4][4] = {};     // g-half accumulators

    // prefetch stages 0..2
    #pragma unroll
    for (int st = 0; st < 3; st++) {
        uint32_t db = sbase + st * 32768u;
        #pragma unroll
        for (int ii = 0; ii < 2; ii++) {
            int c = tid + ii * 256;
            cp16(db +          c * 16, Ah + (size_t)st * 2048 + c * 4);
            cp16(db +  8192u + c * 16, Al + (size_t)st * 2048 + c * 4);
            cp16(db + 16384u + c * 16, Bh + (size_t)st * 2048 + c * 4);
            cp16(db + 24576u + c * 16, Bl + (size_t)st * 2048 + c * 4);
        }
        asm volatile("cp.async.commit_group;");
    }

    for (int kc = 0; kc < 8; kc++) {
        asm volatile("cp.async.wait_group 2;");
        __syncthreads();
        int stg = kc % 3;
        const uint32_t* sAh = sm + stg * 8192;
        const uint32_t* sAl = sAh + 2048;
        const uint32_t* sBh = sAh + 4096;
        const uint32_t* sBl = sAh + 6144;
        #pragma unroll
        for (int ks = 0; ks < 2; ks++) {
            uint32_t ah[2][4], al[2][4];
            #pragma unroll
            for (int mt = 0; mt < 2; mt++) {
                int base = (ks * 8 + wm * 2 + mt) * 128 + lane;
                #pragma unroll
                for (int r = 0; r < 4; r++) {
                    ah[mt][r] = sAh[base + r * 32];
                    al[mt][r] = sAl[base + r * 32];
                }
            }
            #pragma unroll
            for (int i = 0; i < 4; i++) {
                int bidx_a = ((ks * 16 +     wn * 4 + i) * 32 + lane) * 2;
                int bidx_g = ((ks * 16 + 8 + wn * 4 + i) * 32 + lane) * 2;
                uint2 bha = *(const uint2*)&sBh[bidx_a];
                uint2 bla = *(const uint2*)&sBl[bidx_a];
                uint2 bhg = *(const uint2*)&sBh[bidx_g];
                uint2 blg = *(const uint2*)&sBl[bidx_g];
                #pragma unroll
                for (int mt = 0; mt < 2; mt++) {
                    mma_bf16(acca[mt][i], ah[mt], bha.x, bha.y);
                    mma_bf16(acca[mt][i], al[mt], bha.x, bha.y);
                    mma_bf16(acca[mt][i], ah[mt], bla.x, bla.y);
                    mma_bf16(accg[mt][i], ah[mt], bhg.x, bhg.y);
                    mma_bf16(accg[mt][i], al[mt], bhg.x, bhg.y);
                    mma_bf16(accg[mt][i], ah[mt], blg.x, blg.y);
                }
            }
        }
        __syncthreads();
        if (kc < 5) {
            int st = kc + 3;
            uint32_t db = sbase + (st % 3) * 32768u;
            #pragma unroll
            for (int ii = 0; ii < 2; ii++) {
                int c = tid + ii * 256;
                cp16(db +          c * 16, Ah + (size_t)st * 2048 + c * 4);
                cp16(db +  8192u + c * 16, Al + (size_t)st * 2048 + c * 4);
                cp16(db + 16384u + c * 16, Bh + (size_t)st * 2048 + c * 4);
                cp16(db + 24576u + c * 16, Bl + (size_t)st * 2048 + c * 4);
            }
            asm volatile("cp.async.commit_group;");
        } else {
            asm volatile("cp.async.commit_group;");   // keep group count in sync
        }
    }

    // register epilogue: bias + GLU + residual -> g_zr
    const float* brow = bias_all + layer * 512;
    #pragma unroll
    for (int i = 0; i < 4; i++) {
        int cbase = nb * 64 + wn * 32 + i * 8 + (lane & 3) * 2;
        float ba0 = brow[cbase],       ba1 = brow[cbase + 1];
        float bg0 = brow[cbase + 256], bg1 = brow[cbase + 257];
        #pragma unroll
        for (int mt = 0; mt < 2; mt++) {
            int r0 = mb * 128 + wm * 32 + mt * 16 + (lane >> 2);
            #pragma unroll
            for (int half = 0; half < 2; half++) {
                size_t m = (size_t)r0 + half * 8;
                float a0 = acca[mt][i][half * 2 + 0] + ba0;
                float a1 = acca[mt][i][half * 2 + 1] + ba1;
                float g0 = accg[mt][i][half * 2 + 0] + bg0;
                float g1 = accg[mt][i][half * 2 + 1] + bg1;
                float2 hres = *(const float2*)&g_h[m * HH + cbase];
                float2 zo;
                zo.x = a0 / (1.0f + expf(-g0)) + hres.x;
                zo.y = a1 / (1.0f + expf(-g1)) + hres.y;
                *(float2*)&g_zr[m * HH + cbase] = zo;
            }
        }
    }
}

// ---------------------------------------------------------------------------
// LayerNorm over H=256: g_h = LN(g_zr)*gamma + beta.  One warp per row.
// ---------------------------------------------------------------------------
__global__ __launch_bounds__(256) void ln_kernel(
        const float* __restrict__ lng, const float* __restrict__ lnb, int layer) {
    int row  = blockIdx.x * 8 + (threadIdx.x >> 5);
    int lane = threadIdx.x & 31;
    const float* Z = g_zr + (size_t)row * HH;
    float4 v0 = *(const float4*)&Z[lane * 4];
    float4 v1 = *(const float4*)&Z[128 + lane * 4];
    float s  = v0.x + v0.y + v0.z + v0.w + v1.x + v1.y + v1.z + v1.w;
    float ss = v0.x*v0.x + v0.y*v0.y + v0.z*v0.z + v0.w*v0.w
             + v1.x*v1.x + v1.y*v1.y + v1.z*v1.z + v1.w*v1.w;
    #pragma unroll
    for (int o = 16; o; o >>= 1) {
        s  += __shfl_xor_sync(0xffffffffu, s,  o);
        ss += __shfl_xor_sync(0xffffffffu, ss, o);
    }
    float mean = s * (1.0f / 256.0f);
    float var  = ss * (1.0f / 256.0f) - mean * mean;
    float rstd = rsqrtf(var + 1e-5f);
    float* O = g_h + (size_t)row * HH;
    const float* G0 = &lng[layer * HH];
    const float* B0 = &lnb[layer * HH];
    float4 ga = *(const float4*)&G0[lane * 4];
    float4 gb = *(const float4*)&G0[128 + lane * 4];
    float4 ba = *(const float4*)&B0[lane * 4];
    float4 bb = *(const float4*)&B0[128 + lane * 4];
    float4 o0, o1;
    o0.x = (v0.x - mean) * rstd * ga.x + ba.x;
    o0.y = (v0.y - mean) * rstd * ga.y + ba.y;
    o0.z = (v0.z - mean) * rstd * ga.z + ba.z;
    o0.w = (v0.w - mean) * rstd * ga.w + ba.w;
    o1.x = (v1.x - mean) * rstd * gb.x + bb.x;
    o1.y = (v1.y - mean) * rstd * gb.y + bb.y;
    o1.z = (v1.z - mean) * rstd * gb.z + bb.z;
    o1.w = (v1.w - mean) * rstd * gb.w + bb.w;
    *(float4*)&O[lane * 4] = o0;
    *(float4*)&O[128 + lane * 4] = o1;
}

// ---------------------------------------------------------------------------
// Mean pool over L
// ---------------------------------------------------------------------------
__global__ __launch_bounds__(256) void pool_kernel() {
    int b = blockIdx.x, ch = threadIdx.x;
    const float* Hp = g_h + (size_t)b * LL * HH + ch;
    float s0 = 0.f, s1 = 0.f, s2 = 0.f, s3 = 0.f;
    for (int l = 0; l < LL; l += 4) {
        s0 += Hp[(size_t)(l + 0) * HH];
        s1 += Hp[(size_t)(l + 1) * HH];
        s2 += Hp[(size_t)(l + 2) * HH];
        s3 += Hp[(size_t)(l + 3) * HH];
    }
    g_pool[b * HH + ch] = (s0 + s1 + s2 + s3) * (1.0f / LL);
}

// ---------------------------------------------------------------------------
// Decoder MLP: 256 -> 128 relu -> 64 relu -> 32
// ---------------------------------------------------------------------------
__global__ __launch_bounds__(128) void decoder_kernel(
        const float* __restrict__ w1, const float* __restrict__ b1,
        const float* __restrict__ w2, const float* __restrict__ b2,
        const float* __restrict__ w3, const float* __restrict__ b3,
        float* __restrict__ out) {
    __shared__ float p[HH];
    __shared__ float q1[DM1];
    __shared__ float q2[DM2];
    int b = blockIdx.x, tid = threadIdx.x;
    p[tid]       = g_pool[b * HH + tid];
    p[tid + 128] = g_pool[b * HH + tid + 128];
    __syncthreads();
    {
        float s = b1[tid];
        #pragma unroll 4
        for (int k = 0; k < HH; k++) s = fmaf(p[k], w1[k * DM1 + tid], s);
        q1[tid] = fmaxf(s, 0.0f);
    }
    __syncthreads();
    if (tid < DM2) {
        float s = b2[tid];
        #pragma unroll 4
        for (int k = 0; k < DM1; k++) s = fmaf(q1[k], w2[k * DM2 + tid], s);
        q2[tid] = fmaxf(s, 0.0f);
    }
    __syncthreads();
    if (tid < DOUT) {
        float s = b3[tid];
        #pragma unroll 4
        for (int k = 0; k < DM2; k++) s = fmaf(q2[k], w3[k * DOUT + tid], s);
        out[b * DOUT + tid] = s;
    }
}

// ---------------------------------------------------------------------------
extern "C" void kernel_launch(void* const* d_in, const int* in_sizes, int n_in,
                              void* d_out, int out_size) {
    const float* x          = (const float*)d_in[0];
    const float* enc_w      = (const float*)d_in[1];
    const float* enc_b      = (const float*)d_in[2];
    const float* log_dt     = (const float*)d_in[3];
    const float* C_re       = (const float*)d_in[4];
    const float* C_im       = (const float*)d_in[5];
    const float* log_A_real = (const float*)d_in[6];
    const float* A_imag     = (const float*)d_in[7];
    const float* D_skip     = (const float*)d_in[8];
    const float* w_out      = (const float*)d_in[9];
    const float* b_out      = (const float*)d_in[10];
    const float* ln_g       = (const float*)d_in[11];
    const float* ln_b       = (const float*)d_in[12];
    const float* dec_w1     = (const float*)d_in[13];
    const float* dec_b1     = (const float*)d_in[14];
    const float* dec_w2     = (const float*)d_in[15];
    const float* dec_b2     = (const float*)d_in[16];
    const float* dec_w3     = (const float*)d_in[17];
    const float* dec_b3     = (const float*)d_in[18];
    float* out = (float*)d_out;

    cudaFuncSetAttribute(gemm_glu_tc,
                         cudaFuncAttributeMaxDynamicSharedMemorySize, GEMM_SMEM);

    prep_w_kernel<<<(NLAYERS * 512 * 128 + 255) / 256, 256>>>(w_out);
    dim3 enc_grid(MROWS / 64, HH / 64);
    encoder_kernel<<<enc_grid, 256>>>(x, enc_w, enc_b);
    dim3 p1_grid(BB, HH / 16, NCHUNK - 1);
    dim3 p2_grid(BB, HH / 16, NCHUNK);
    for (int layer = 0; layer < NLAYERS; layer++) {
        scan_p1<<<p1_grid, 128>>>(log_dt, log_A_real, A_imag, layer);
        scan_comb<<<BB * HH * NH / 256, 256>>>(log_dt, log_A_real, A_imag, layer);
        scan_p2<<<p2_grid, 128>>>(log_dt, C_re, C_im,
                                  log_A_real, A_imag, D_skip, layer);
        gemm_glu_tc<<<dim3(NMBLK, 4), 256, GEMM_SMEM>>>(b_out, layer);
        ln_kernel<<<MROWS / 8, 256>>>(ln_g, ln_b, layer);
    }
    pool_kernel<<<BB, 256>>>();
    decoder_kernel<<<BB, 128>>>(dec_w1, dec_b1, dec_w2, dec_b2, dec_w3, dec_b3, out);
}

// round 9
// speedup vs baseline: 1.9770x; 1.0353x over previous
#include <cuda_runtime.h>
#include <cuda_bf16.h>
#include <cstdint>
#include <math.h>

#define BB 16
#define LL 2048
#define DIN 64
#define HH 256
#define NH 32
#define NLAYERS 4
#define DM1 128
#define DM2 64
#define DOUT 32

#define MROWS (BB*LL)          // 32768
#define NMBLK (MROWS/128)      // 256 row blocks

#define NCHUNK 16
#define CLEN (LL/NCHUNK)       // 128

// Scratch (allocation-free contract: __device__ globals)
__device__ float g_h  [MROWS*HH];                // hidden state (B*L, H)
__device__ float g_zr [MROWS*HH];                // glu + residual (pre-LN)
// A fragments (bf16 pairs): [mblock(256)][kchunk(8)][ks(2)][mtile(8)][lane(32)][reg(4)]
__device__ __align__(16) uint32_t g_af_hi[(size_t)NMBLK*16384];
__device__ __align__(16) uint32_t g_af_lo[(size_t)NMBLK*16384];
// B fragments (bf16 pairs): [layer][nb(4)][kchunk(8)][ks(2)][nt(16)][lane(32)][reg(2)]
__device__ __align__(16) uint32_t g_wf_hi[(size_t)NLAYERS*4*16384];
__device__ __align__(16) uint32_t g_wf_lo[(size_t)NLAYERS*4*16384];
// scan carries: [chunk][b][ch][state] complex
__device__ float2 g_carry[(size_t)NCHUNK*BB*HH*NH];
__device__ float g_poolp[BB*16*HH];
__device__ float g_pool[BB*HH];

// ---------------------------------------------------------------------------
// helpers
// ---------------------------------------------------------------------------
__device__ __forceinline__ uint32_t smem_u32(const void* p) {
    uint32_t a;
    asm("{ .reg .u64 t; cvta.to.shared.u64 t, %1; cvt.u32.u64 %0, t; }"
        : "=r"(a) : "l"(p));
    return a;
}
__device__ __forceinline__ unsigned short bfu(float x) {
    return __bfloat16_as_ushort(__float2bfloat16_rn(x));
}
__device__ __forceinline__ float bff(unsigned short u) {
    return __bfloat162float(__ushort_as_bfloat16(u));
}
__device__ __forceinline__ void cp16(uint32_t dst, const void* src) {
    asm volatile("cp.async.cg.shared.global [%0], [%1], 16;"
                 :: "r"(dst), "l"(src));
}
__device__ __forceinline__ void mma_bf16(float* d, const uint32_t* a,
                                         uint32_t b0, uint32_t b1) {
    asm volatile(
        "mma.sync.aligned.m16n8k16.row.col.f32.bf16.bf16.f32 "
        "{%0,%1,%2,%3}, {%4,%5,%6,%7}, {%8,%9}, {%0,%1,%2,%3};"
        : "+f"(d[0]), "+f"(d[1]), "+f"(d[2]), "+f"(d[3])
        : "r"(a[0]), "r"(a[1]), "r"(a[2]), "r"(a[3]), "r"(b0), "r"(b1));
}

// ---------------------------------------------------------------------------
// Weight prep: bf16x3 split of w_out into fragment-ordered g_wf_hi/lo.
// ---------------------------------------------------------------------------
__global__ __launch_bounds__(256) void prep_w_kernel(const float* __restrict__ w) {
    int i = blockIdx.x * 256 + threadIdx.x;
    if (i >= NLAYERS * 512 * 128) return;
    int hp = i & 127;          int h = hp * 2;
    int o  = (i >> 7) & 511;
    int layer = i >> 16;
    float v0 = w[((size_t)(layer * 512) + o) * 256 + h];
    float v1 = w[((size_t)(layer * 512) + o) * 256 + h + 1];
    unsigned short h0 = bfu(v0), h1 = bfu(v1);
    unsigned short l0 = bfu(v0 - bff(h0)), l1 = bfu(v1 - bff(h1));
    int half = o >> 8;
    int nb   = (o & 255) >> 6;
    int nt   = ((o >> 3) & 7) | (half << 3);
    int gid  = o & 7;
    int kchunk = h >> 5;
    int ks   = (h >> 4) & 1;
    int kk   = h & 15;
    int tig  = (kk & 7) >> 1;
    int reg  = kk >> 3;
    int lane = gid * 4 + tig;
    size_t idx = (((((size_t)(layer * 4 + nb) * 8 + kchunk) * 2 + ks) * 16 + nt) * 32 + lane) * 2 + reg;
    g_wf_hi[idx] = (uint32_t)h0 | ((uint32_t)h1 << 16);
    g_wf_lo[idx] = (uint32_t)l0 | ((uint32_t)l1 << 16);
}

// ---------------------------------------------------------------------------
// Encoder: g_h[m, n] = x[m, :64] @ enc_w[:, n] + enc_b[n]  (fp32 SIMT, small)
// ---------------------------------------------------------------------------
__global__ __launch_bounds__(256) void encoder_kernel(
        const float* __restrict__ X, const float* __restrict__ W,
        const float* __restrict__ bias) {
    __shared__ float As[64][36];
    __shared__ float Bs[32][68];
    int row0 = blockIdx.x * 64;
    int n0   = blockIdx.y * 64;
    int tid = threadIdx.x;
    int tx = tid & 15, ty = tid >> 4;
    float acc[4][4] = {};
    for (int k0 = 0; k0 < DIN; k0 += 32) {
        #pragma unroll
        for (int p = 0; p < 2; p++) {
            int q = tid + p * 256;
            int r = q >> 3, kq = q & 7;
            float4 v = *(const float4*)&X[(row0 + r) * DIN + k0 + kq * 4];
            *(float4*)&As[r][kq * 4] = v;
        }
        #pragma unroll
        for (int p = 0; p < 2; p++) {
            int q = tid + p * 256;
            int kk = q >> 4, nq = q & 15;
            float4 v = *(const float4*)&W[(k0 + kk) * HH + n0 + nq * 4];
            *(float4*)&Bs[kk][nq * 4] = v;
        }
        __syncthreads();
        #pragma unroll
        for (int k = 0; k < 32; k++) {
            float a[4];
            #pragma unroll
            for (int i = 0; i < 4; i++) a[i] = As[ty * 4 + i][k];
            float4 bv = *(const float4*)&Bs[k][tx * 4];
            float bj[4] = {bv.x, bv.y, bv.z, bv.w};
            #pragma unroll
            for (int i = 0; i < 4; i++)
                #pragma unroll
                for (int j = 0; j < 4; j++)
                    acc[i][j] = fmaf(a[i], bj[j], acc[i][j]);
        }
        __syncthreads();
    }
    #pragma unroll
    for (int i = 0; i < 4; i++) {
        int m = row0 + ty * 4 + i;
        #pragma unroll
        for (int j = 0; j < 4; j++) {
            int n = n0 + tx * 4 + j;
            g_h[m * HH + n] = acc[i][j] + bias[n];
        }
    }
}

// ---------------------------------------------------------------------------
// Scan phase 1: per-chunk local recurrence from zero state; saves end state.
// grid (B, H/16, NCHUNK-1), block 128.
// ---------------------------------------------------------------------------
__global__ __launch_bounds__(128) void scan_p1(
        const float* __restrict__ log_dt, const float* __restrict__ log_A_real,
        const float* __restrict__ A_imag, int layer) {
    __shared__ float s_in[128 * 16];
    int b   = blockIdx.x;
    int ch0 = blockIdx.y * 16;
    int chunk = blockIdx.z;
    int tid = threadIdx.x;
    int warp = tid >> 5, lane = tid & 31;
    int g = lane >> 3, j = lane & 7;
    int c_local = warp * 4 + g;
    int ch = ch0 + c_local;

    float dt = expf(log_dt[layer * HH + ch]);
    float w_re[4], w_im[4], s_re[4], s_im[4];
    #pragma unroll
    for (int k = 0; k < 4; k++) {
        int n = j * 4 + k;
        int idx = (layer * HH + ch) * NH + n;
        float Are = -expf(log_A_real[idx]);
        float Aim = A_imag[idx];
        float er  = expf(dt * Are);
        w_re[k] = er * cosf(dt * Aim);
        w_im[k] = er * sinf(dt * Aim);
        s_re[k] = 0.0f; s_im[k] = 0.0f;
    }

    const float* hin = g_h + (size_t)b * LL * HH + (size_t)chunk * CLEN * HH;
    #pragma unroll
    for (int p = 0; p < 4; p++) {
        int q = tid + p * 128;
        int t = q >> 2, cq = q & 3;
        float4 v = *(const float4*)&hin[t * HH + ch0 + cq * 4];
        *(float4*)&s_in[t * 16 + cq * 4] = v;
    }
    __syncthreads();
    #pragma unroll 8
    for (int t = 0; t < CLEN; t++) {
        float u = s_in[t * 16 + c_local];
        #pragma unroll
        for (int k = 0; k < 4; k++) {
            float nr = fmaf(w_re[k], s_re[k], u);
            nr = fmaf(-w_im[k], s_im[k], nr);
            float ni = w_re[k] * s_im[k];
            ni = fmaf(w_im[k], s_re[k], ni);
            s_re[k] = nr; s_im[k] = ni;
        }
    }
    size_t cbase = ((size_t)(chunk * BB + b) * HH + ch) * NH + j * 4;
    #pragma unroll
    for (int k = 0; k < 4; k++)
        g_carry[cbase + k] = make_float2(s_re[k], s_im[k]);
}

// ---------------------------------------------------------------------------
// Scan combine: sequentially propagate carries across chunks.
// ---------------------------------------------------------------------------
__global__ __launch_bounds__(256) void scan_comb(
        const float* __restrict__ log_dt, const float* __restrict__ log_A_real,
        const float* __restrict__ A_imag, int layer) {
    int gi = blockIdx.x * 256 + threadIdx.x;     // (b*HH + ch)*NH + n
    int n  = gi & 31;
    int ch = (gi >> 5) & 255;
    float dt = expf(log_dt[layer * HH + ch]);
    int idxp = (layer * HH + ch) * NH + n;
    float Are = -expf(log_A_real[idxp]);
    float Aim = A_imag[idxp];
    float er  = expf((float)CLEN * dt * Are);
    float ang = (float)CLEN * dt * Aim;
    float wp_re = er * cosf(ang);
    float wp_im = er * sinf(ang);
    float cs_re = 0.0f, cs_im = 0.0f;
    #pragma unroll
    for (int c = 0; c < NCHUNK; c++) {
        size_t idx = (size_t)c * (BB * HH * NH) + gi;
        float2 se = g_carry[idx];
        g_carry[idx] = make_float2(cs_re, cs_im);
        float nr = wp_re * cs_re - wp_im * cs_im + se.x;
        float ni = wp_re * cs_im + wp_im * cs_re + se.y;
        cs_re = nr; cs_im = ni;
    }
}

// ---------------------------------------------------------------------------
// Scan phase 2: per-chunk scan from true carry; fused D-skip + GELU +
// bf16x3 fragment emission (smem-staged, coalesced STG.128).
// grid (B, H/16, NCHUNK), block 128.
// ---------------------------------------------------------------------------
__global__ __launch_bounds__(128) void scan_p2(
        const float* __restrict__ log_dt, const float* __restrict__ C_re,
        const float* __restrict__ C_im,   const float* __restrict__ log_A_real,
        const float* __restrict__ A_imag, const float* __restrict__ D_skip,
        int layer) {
    __shared__ float s_in [128 * 16];
    __shared__ float s_out[128 * 16];
    __shared__ uint32_t s_fh[1024];
    __shared__ uint32_t s_fl[1024];
    int b   = blockIdx.x;
    int ch0 = blockIdx.y * 16;
    int chunk = blockIdx.z;
    int tid = threadIdx.x;
    int warp = tid >> 5, lane = tid & 31;
    int g = lane >> 3, j = lane & 7;
    int c_local = warp * 4 + g;
    int ch = ch0 + c_local;

    float dt  = expf(log_dt[layer * HH + ch]);
    float dsk = D_skip[layer * HH + ch];
    float w_re[4], w_im[4], ck_re[4], ck_im[4], s_re[4], s_im[4];
    size_t cbase = ((size_t)(chunk * BB + b) * HH + ch) * NH + j * 4;
    #pragma unroll
    for (int k = 0; k < 4; k++) {
        int n = j * 4 + k;
        int idx = (layer * HH + ch) * NH + n;
        float Are = -expf(log_A_real[idx]);
        float Aim = A_imag[idx];
        float er  = expf(dt * Are);
        float wre = er * cosf(dt * Aim);
        float wim = er * sinf(dt * Aim);
        w_re[k] = wre; w_im[k] = wim;
        float nre = wre - 1.0f, nim = wim;
        float inv = 1.0f / (Are * Are + Aim * Aim);
        float ire = Are * inv, iim = -Aim * inv;
        float tre = nre * ire - nim * iim;
        float tim = nre * iim + nim * ire;
        float cre = C_re[idx], cim = C_im[idx];
        ck_re[k] = 2.0f * (cre * tre - cim * tim);
        ck_im[k] = 2.0f * (cre * tim + cim * tre);
        float2 cs = (chunk == 0) ? make_float2(0.0f, 0.0f) : g_carry[cbase + k];
        s_re[k] = cs.x; s_im[k] = cs.y;
    }

    const float* hin = g_h + (size_t)b * LL * HH + (size_t)chunk * CLEN * HH;

    #pragma unroll
    for (int p = 0; p < 4; p++) {
        int q = tid + p * 128;
        int t = q >> 2, cq = q & 3;
        float4 v = *(const float4*)&hin[t * HH + ch0 + cq * 4];
        *(float4*)&s_in[t * 16 + cq * 4] = v;
    }
    __syncthreads();
    #pragma unroll 4
    for (int t = 0; t < CLEN; t++) {
        float u = s_in[t * 16 + c_local];
        float pacc = 0.0f;
        #pragma unroll
        for (int k = 0; k < 4; k++) {
            float nr = fmaf(w_re[k], s_re[k], u);
            nr = fmaf(-w_im[k], s_im[k], nr);
            float ni = w_re[k] * s_im[k];
            ni = fmaf(w_im[k], s_re[k], ni);
            s_re[k] = nr; s_im[k] = ni;
            pacc = fmaf(ck_re[k], nr, pacc);
            pacc = fmaf(-ck_im[k], ni, pacc);
        }
        pacc += __shfl_xor_sync(0xffffffffu, pacc, 1);
        pacc += __shfl_xor_sync(0xffffffffu, pacc, 2);
        pacc += __shfl_xor_sync(0xffffffffu, pacc, 4);
        if (j == 0)
            s_out[t * 16 + c_local] = fmaf(u, dsk, pacc);
    }
    __syncthreads();
    // GELU + bf16x3 split + pack into staged fragment slice
    // Block covers exactly one mblk x one (kchunk, ks) slice of g_af_*.
    #pragma unroll
    for (int p = 0; p < 4; p++) {
        int q = tid + p * 128;
        int t = q >> 2, cq = q & 3;
        float4 v = *(const float4*)&s_out[t * 16 + cq * 4];
        v.x = 0.5f * v.x * (1.0f + erff(v.x * 0.70710678118654752f));
        v.y = 0.5f * v.y * (1.0f + erff(v.y * 0.70710678118654752f));
        v.z = 0.5f * v.z * (1.0f + erff(v.z * 0.70710678118654752f));
        v.w = 0.5f * v.w * (1.0f + erff(v.w * 0.70710678118654752f));
        int mtile  = t >> 4;
        int rowsel = (t >> 3) & 1;
        int gid    = t & 7;
        int kk     = cq * 4;                 // k offset within the 16-wide slice
        int tig0   = (kk & 7) >> 1;
        int reg    = rowsel + ((kk >> 3) << 1);
        int base   = (mtile * 32 + gid * 4 + tig0) * 4 + reg;
        unsigned short hx = bfu(v.x), hy = bfu(v.y), hz = bfu(v.z), hw = bfu(v.w);
        unsigned short lx = bfu(v.x - bff(hx)), ly = bfu(v.y - bff(hy));
        unsigned short lz = bfu(v.z - bff(hz)), lw = bfu(v.w - bff(hw));
        s_fh[base]     = (uint32_t)hx | ((uint32_t)hy << 16);
        s_fh[base + 4] = (uint32_t)hz | ((uint32_t)hw << 16);
        s_fl[base]     = (uint32_t)lx | ((uint32_t)ly << 16);
        s_fl[base + 4] = (uint32_t)lz | ((uint32_t)lw << 16);
    }
    __syncthreads();
    int mblk   = (b * LL + chunk * CLEN) >> 7;
    int kchunk = ch0 >> 5;
    int ks     = (ch0 >> 4) & 1;
    size_t gb = (size_t)mblk * 16384 + (size_t)(kchunk * 2 + ks) * 1024;
    #pragma unroll
    for (int p = 0; p < 2; p++) {
        int i = (tid + p * 128) * 4;
        *(uint4*)&g_af_hi[gb + i] = *(const uint4*)&s_fh[i];
        *(uint4*)&g_af_lo[gb + i] = *(const uint4*)&s_fl[i];
    }
}

// ---------------------------------------------------------------------------
// bf16x3 warp-MMA GEMM, register-GLU epilogue, 3-stage cp.async pipeline.
// A fragments now [mtile][lane][reg4] -> one LDS.128 per fragment.
// ---------------------------------------------------------------------------
#define GEMM_SMEM 98304
__global__ __launch_bounds__(256, 2) void gemm_glu_tc(
        const float* __restrict__ bias_all, int layer) {
    extern __shared__ uint32_t sm[];
    int tid = threadIdx.x, lane = tid & 31, wid = tid >> 5;
    int wm = wid & 3, wn = wid >> 2;
    int mb = blockIdx.x, nb = blockIdx.y;
    uint32_t sbase = smem_u32(sm);

    const uint32_t* Ah = g_af_hi + (size_t)mb * 16384;
    const uint32_t* Al = g_af_lo + (size_t)mb * 16384;
    const uint32_t* Bh = g_wf_hi + (size_t)(layer * 4 + nb) * 16384;
    const uint32_t* Bl = g_wf_lo + (size_t)(layer * 4 + nb) * 16384;

    float acca[2][4][4] = {};     // a-half accumulators
    float accg[2][4][4] = {};     // g-half accumulators

    // prefetch stages 0..2
    #pragma unroll
    for (int st = 0; st < 3; st++) {
        uint32_t db = sbase + st * 32768u;
        #pragma unroll
        for (int ii = 0; ii < 2; ii++) {
            int c = tid + ii * 256;
            cp16(db +          c * 16, Ah + (size_t)st * 2048 + c * 4);
            cp16(db +  8192u + c * 16, Al + (size_t)st * 2048 + c * 4);
            cp16(db + 16384u + c * 16, Bh + (size_t)st * 2048 + c * 4);
            cp16(db + 24576u + c * 16, Bl + (size_t)st * 2048 + c * 4);
        }
        asm volatile("cp.async.commit_group;");
    }

    for (int kc = 0; kc < 8; kc++) {
        asm volatile("cp.async.wait_group 2;");
        __syncthreads();
        int stg = kc % 3;
        const uint32_t* sAh = sm + stg * 8192;
        const uint32_t* sAl = sAh + 2048;
        const uint32_t* sBh = sAh + 4096;
        const uint32_t* sBl = sAh + 6144;
        #pragma unroll
        for (int ks = 0; ks < 2; ks++) {
            uint32_t ah[2][4], al[2][4];
            #pragma unroll
            for (int mt = 0; mt < 2; mt++) {
                int base = (ks * 8 + wm * 2 + mt) * 128 + lane * 4;
                uint4 qh = *(const uint4*)&sAh[base];
                uint4 ql = *(const uint4*)&sAl[base];
                ah[mt][0] = qh.x; ah[mt][1] = qh.y; ah[mt][2] = qh.z; ah[mt][3] = qh.w;
                al[mt][0] = ql.x; al[mt][1] = ql.y; al[mt][2] = ql.z; al[mt][3] = ql.w;
            }
            #pragma unroll
            for (int i = 0; i < 4; i++) {
                int bidx_a = ((ks * 16 +     wn * 4 + i) * 32 + lane) * 2;
                int bidx_g = ((ks * 16 + 8 + wn * 4 + i) * 32 + lane) * 2;
                uint2 bha = *(const uint2*)&sBh[bidx_a];
                uint2 bla = *(const uint2*)&sBl[bidx_a];
                uint2 bhg = *(const uint2*)&sBh[bidx_g];
                uint2 blg = *(const uint2*)&sBl[bidx_g];
                #pragma unroll
                for (int mt = 0; mt < 2; mt++) {
                    mma_bf16(acca[mt][i], ah[mt], bha.x, bha.y);
                    mma_bf16(acca[mt][i], al[mt], bha.x, bha.y);
                    mma_bf16(acca[mt][i], ah[mt], bla.x, bla.y);
                    mma_bf16(accg[mt][i], ah[mt], bhg.x, bhg.y);
                    mma_bf16(accg[mt][i], al[mt], bhg.x, bhg.y);
                    mma_bf16(accg[mt][i], ah[mt], blg.x, blg.y);
                }
            }
        }
        __syncthreads();
        if (kc < 5) {
            int st = kc + 3;
            uint32_t db = sbase + (st % 3) * 32768u;
            #pragma unroll
            for (int ii = 0; ii < 2; ii++) {
                int c = tid + ii * 256;
                cp16(db +          c * 16, Ah + (size_t)st * 2048 + c * 4);
                cp16(db +  8192u + c * 16, Al + (size_t)st * 2048 + c * 4);
                cp16(db + 16384u + c * 16, Bh + (size_t)st * 2048 + c * 4);
                cp16(db + 24576u + c * 16, Bl + (size_t)st * 2048 + c * 4);
            }
            asm volatile("cp.async.commit_group;");
        } else {
            asm volatile("cp.async.commit_group;");   // keep group count in sync
        }
    }

    // register epilogue: bias + GLU + residual -> g_zr
    const float* brow = bias_all + layer * 512;
    #pragma unroll
    for (int i = 0; i < 4; i++) {
        int cbase = nb * 64 + wn * 32 + i * 8 + (lane & 3) * 2;
        float ba0 = brow[cbase],       ba1 = brow[cbase + 1];
        float bg0 = brow[cbase + 256], bg1 = brow[cbase + 257];
        #pragma unroll
        for (int mt = 0; mt < 2; mt++) {
            int r0 = mb * 128 + wm * 32 + mt * 16 + (lane >> 2);
            #pragma unroll
            for (int half = 0; half < 2; half++) {
                size_t m = (size_t)r0 + half * 8;
                float a0 = acca[mt][i][half * 2 + 0] + ba0;
                float a1 = acca[mt][i][half * 2 + 1] + ba1;
                float g0 = accg[mt][i][half * 2 + 0] + bg0;
                float g1 = accg[mt][i][half * 2 + 1] + bg1;
                float2 hres = *(const float2*)&g_h[m * HH + cbase];
                float2 zo;
                zo.x = a0 / (1.0f + expf(-g0)) + hres.x;
                zo.y = a1 / (1.0f + expf(-g1)) + hres.y;
                *(float2*)&g_zr[m * HH + cbase] = zo;
            }
        }
    }
}

// ---------------------------------------------------------------------------
// LayerNorm over H=256: g_h = LN(g_zr)*gamma + beta.  One warp per row.
// ---------------------------------------------------------------------------
__global__ __launch_bounds__(256) void ln_kernel(
        const float* __restrict__ lng, const float* __restrict__ lnb, int layer) {
    int row  = blockIdx.x * 8 + (threadIdx.x >> 5);
    int lane = threadIdx.x & 31;
    const float* Z = g_zr + (size_t)row * HH;
    float4 v0 = *(const float4*)&Z[lane * 4];
    float4 v1 = *(const float4*)&Z[128 + lane * 4];
    float s  = v0.x + v0.y + v0.z + v0.w + v1.x + v1.y + v1.z + v1.w;
    float ss = v0.x*v0.x + v0.y*v0.y + v0.z*v0.z + v0.w*v0.w
             + v1.x*v1.x + v1.y*v1.y + v1.z*v1.z + v1.w*v1.w;
    #pragma unroll
    for (int o = 16; o; o >>= 1) {
        s  += __shfl_xor_sync(0xffffffffu, s,  o);
        ss += __shfl_xor_sync(0xffffffffu, ss, o);
    }
    float mean = s * (1.0f / 256.0f);
    float var  = ss * (1.0f / 256.0f) - mean * mean;
    float rstd = rsqrtf(var + 1e-5f);
    float* O = g_h + (size_t)row * HH;
    const float* G0 = &lng[layer * HH];
    const float* B0 = &lnb[layer * HH];
    float4 ga = *(const float4*)&G0[lane * 4];
    float4 gb = *(const float4*)&G0[128 + lane * 4];
    float4 ba = *(const float4*)&B0[lane * 4];
    float4 bb = *(const float4*)&B0[128 + lane * 4];
    float4 o0, o1;
    o0.x = (v0.x - mean) * rstd * ga.x + ba.x;
    o0.y = (v0.y - mean) * rstd * ga.y + ba.y;
    o0.z = (v0.z - mean) * rstd * ga.z + ba.z;
    o0.w = (v0.w - mean) * rstd * ga.w + ba.w;
    o1.x = (v1.x - mean) * rstd * gb.x + bb.x;
    o1.y = (v1.y - mean) * rstd * gb.y + bb.y;
    o1.z = (v1.z - mean) * rstd * gb.z + bb.z;
    o1.w = (v1.w - mean) * rstd * gb.w + bb.w;
    *(float4*)&O[lane * 4] = o0;
    *(float4*)&O[128 + lane * 4] = o1;
}

// ---------------------------------------------------------------------------
// Two-phase mean pool over L
// ---------------------------------------------------------------------------
__global__ __launch_bounds__(256) void pool1_kernel() {
    int b = blockIdx.x, seg = blockIdx.y, ch = threadIdx.x;
    const float* Hp = g_h + ((size_t)b * LL + (size_t)seg * 128) * HH + ch;
    float s0 = 0.f, s1 = 0.f, s2 = 0.f, s3 = 0.f;
    for (int l = 0; l < 128; l += 4) {
        s0 += Hp[(size_t)(l + 0) * HH];
        s1 += Hp[(size_t)(l + 1) * HH];
        s2 += Hp[(size_t)(l + 2) * HH];
        s3 += Hp[(size_t)(l + 3) * HH];
    }
    g_poolp[(b * 16 + seg) * HH + ch] = s0 + s1 + s2 + s3;
}
__global__ __launch_bounds__(256) void pool2_kernel() {
    int b = blockIdx.x, ch = threadIdx.x;
    float s = 0.f;
    #pragma unroll
    for (int seg = 0; seg < 16; seg++)
        s += g_poolp[(b * 16 + seg) * HH + ch];
    g_pool[b * HH + ch] = s * (1.0f / LL);
}

// ---------------------------------------------------------------------------
// Decoder MLP: 256 -> 128 relu -> 64 relu -> 32
// ---------------------------------------------------------------------------
__global__ __launch_bounds__(128) void decoder_kernel(
        const float* __restrict__ w1, const float* __restrict__ b1,
        const float* __restrict__ w2, const float* __restrict__ b2,
        const float* __restrict__ w3, const float* __restrict__ b3,
        float* __restrict__ out) {
    __shared__ float p[HH];
    __shared__ float q1[DM1];
    __shared__ float q2[DM2];
    int b = blockIdx.x, tid = threadIdx.x;
    p[tid]       = g_pool[b * HH + tid];
    p[tid + 128] = g_pool[b * HH + tid + 128];
    __syncthreads();
    {
        float s = b1[tid];
        #pragma unroll 4
        for (int k = 0; k < HH; k++) s = fmaf(p[k], w1[k * DM1 + tid], s);
        q1[tid] = fmaxf(s, 0.0f);
    }
    __syncthreads();
    if (tid < DM2) {
        float s = b2[tid];
        #pragma unroll 4
        for (int k = 0; k < DM1; k++) s = fmaf(q1[k], w2[k * DM2 + tid], s);
        q2[tid] = fmaxf(s, 0.0f);
    }
    __syncthreads();
    if (tid < DOUT) {
        float s = b3[tid];
        #pragma unroll 4
        for (int k = 0; k < DM2; k++) s = fmaf(q2[k], w3[k * DOUT + tid], s);
        out[b * DOUT + tid] = s;
    }
}

// ---------------------------------------------------------------------------
extern "C" void kernel_launch(void* const* d_in, const int* in_sizes, int n_in,
                              void* d_out, int out_size) {
    const float* x          = (const float*)d_in[0];
    const float* enc_w      = (const float*)d_in[1];
    const float* enc_b      = (const float*)d_in[2];
    const float* log_dt     = (const float*)d_in[3];
    const float* C_re       = (const float*)d_in[4];
    const float* C_im       = (const float*)d_in[5];
    const float* log_A_real = (const float*)d_in[6];
    const float* A_imag     = (const float*)d_in[7];
    const float* D_skip     = (const float*)d_in[8];
    const float* w_out      = (const float*)d_in[9];
    const float* b_out      = (const float*)d_in[10];
    const float* ln_g       = (const float*)d_in[11];
    const float* ln_b       = (const float*)d_in[12];
    const float* dec_w1     = (const float*)d_in[13];
    const float* dec_b1     = (const float*)d_in[14];
    const float* dec_w2     = (const float*)d_in[15];
    const float* dec_b2     = (const float*)d_in[16];
    const float* dec_w3     = (const float*)d_in[17];
    const float* dec_b3     = (const float*)d_in[18];
    float* out = (float*)d_out;

    cudaFuncSetAttribute(gemm_glu_tc,
                         cudaFuncAttributeMaxDynamicSharedMemorySize, GEMM_SMEM);

    prep_w_kernel<<<(NLAYERS * 512 * 128 + 255) / 256, 256>>>(w_out);
    dim3 enc_grid(MROWS / 64, HH / 64);
    encoder_kernel<<<enc_grid, 256>>>(x, enc_w, enc_b);
    dim3 p1_grid(BB, HH / 16, NCHUNK - 1);
    dim3 p2_grid(BB, HH / 16, NCHUNK);
    for (int layer = 0; layer < NLAYERS; layer++) {
        scan_p1<<<p1_grid, 128>>>(log_dt, log_A_real, A_imag, layer);
        scan_comb<<<BB * HH * NH / 256, 256>>>(log_dt, log_A_real, A_imag, layer);
        scan_p2<<<p2_grid, 128>>>(log_dt, C_re, C_im,
                                  log_A_real, A_imag, D_skip, layer);
        gemm_glu_tc<<<dim3(NMBLK, 4), 256, GEMM_SMEM>>>(b_out, layer);
        ln_kernel<<<MROWS / 8, 256>>>(ln_g, ln_b, layer);
    }
    pool1_kernel<<<dim3(BB, 16), 256>>>();
    pool2_kernel<<<BB, 256>>>();
    decoder_kernel<<<BB, 128>>>(dec_w1, dec_b1, dec_w2, dec_b2, dec_w3, dec_b3, out);
}

// round 10
// speedup vs baseline: 2.0346x; 1.0291x over previous
#include <cuda_runtime.h>
#include <cuda_bf16.h>
#include <cstdint>
#include <math.h>

#define BB 16
#define LL 2048
#define DIN 64
#define HH 256
#define NH 32
#define NLAYERS 4
#define DM1 128
#define DM2 64
#define DOUT 32

#define MROWS (BB*LL)          // 32768
#define NMBLK (MROWS/128)      // 256 row blocks

#define NCHUNK 16
#define CLEN (LL/NCHUNK)       // 128

typedef unsigned long long u64;

// Scratch (allocation-free contract: __device__ globals)
__device__ float g_h  [MROWS*HH];                // hidden state (B*L, H)
__device__ float g_zr [MROWS*HH];                // glu + residual (pre-LN)
// A fragments (bf16 pairs): [mblock(256)][kchunk(8)][ks(2)][mtile(8)][lane(32)][reg(4)]
__device__ __align__(16) uint32_t g_af_hi[(size_t)NMBLK*16384];
__device__ __align__(16) uint32_t g_af_lo[(size_t)NMBLK*16384];
// B fragments (bf16 pairs): [layer][nb(4)][kchunk(8)][ks(2)][nt(16)][lane(32)][reg(2)]
__device__ __align__(16) uint32_t g_wf_hi[(size_t)NLAYERS*4*16384];
__device__ __align__(16) uint32_t g_wf_lo[(size_t)NLAYERS*4*16384];
// scan carries: [chunk][b][ch][state] complex
__device__ float2 g_carry[(size_t)NCHUNK*BB*HH*NH];
__device__ float g_poolp[BB*16*HH];
__device__ float g_pool[BB*HH];

// ---------------------------------------------------------------------------
// helpers
// ---------------------------------------------------------------------------
__device__ __forceinline__ uint32_t smem_u32(const void* p) {
    uint32_t a;
    asm("{ .reg .u64 t; cvta.to.shared.u64 t, %1; cvt.u32.u64 %0, t; }"
        : "=r"(a) : "l"(p));
    return a;
}
__device__ __forceinline__ unsigned short bfu(float x) {
    return __bfloat16_as_ushort(__float2bfloat16_rn(x));
}
__device__ __forceinline__ float bff(unsigned short u) {
    return __bfloat162float(__ushort_as_bfloat16(u));
}
__device__ __forceinline__ void cp16(uint32_t dst, const void* src) {
    asm volatile("cp.async.cg.shared.global [%0], [%1], 16;"
                 :: "r"(dst), "l"(src));
}
__device__ __forceinline__ void mma_bf16(float* d, const uint32_t* a,
                                         uint32_t b0, uint32_t b1) {
    asm volatile(
        "mma.sync.aligned.m16n8k16.row.col.f32.bf16.bf16.f32 "
        "{%0,%1,%2,%3}, {%4,%5,%6,%7}, {%8,%9}, {%0,%1,%2,%3};"
        : "+f"(d[0]), "+f"(d[1]), "+f"(d[2]), "+f"(d[3])
        : "r"(a[0]), "r"(a[1]), "r"(a[2]), "r"(a[3]), "r"(b0), "r"(b1));
}
// packed fp32x2 (PTX ISA 8.6, sm_100 baseline)
__device__ __forceinline__ u64 pk2(float lo, float hi) {
    u64 r; asm("mov.b64 %0, {%1, %2};" : "=l"(r) : "f"(lo), "f"(hi)); return r;
}
__device__ __forceinline__ void upk2(float& lo, float& hi, u64 v) {
    asm("mov.b64 {%0, %1}, %2;" : "=f"(lo), "=f"(hi) : "l"(v));
}
__device__ __forceinline__ u64 fma2(u64 a, u64 b, u64 c) {
    u64 d; asm("fma.rn.f32x2 %0, %1, %2, %3;" : "=l"(d) : "l"(a), "l"(b), "l"(c));
    return d;
}

// ---------------------------------------------------------------------------
// Weight prep: bf16x3 split of w_out into fragment-ordered g_wf_hi/lo.
// ---------------------------------------------------------------------------
__global__ __launch_bounds__(256) void prep_w_kernel(const float* __restrict__ w) {
    int i = blockIdx.x * 256 + threadIdx.x;
    if (i >= NLAYERS * 512 * 128) return;
    int hp = i & 127;          int h = hp * 2;
    int o  = (i >> 7) & 511;
    int layer = i >> 16;
    float v0 = w[((size_t)(layer * 512) + o) * 256 + h];
    float v1 = w[((size_t)(layer * 512) + o) * 256 + h + 1];
    unsigned short h0 = bfu(v0), h1 = bfu(v1);
    unsigned short l0 = bfu(v0 - bff(h0)), l1 = bfu(v1 - bff(h1));
    int half = o >> 8;
    int nb   = (o & 255) >> 6;
    int nt   = ((o >> 3) & 7) | (half << 3);
    int gid  = o & 7;
    int kchunk = h >> 5;
    int ks   = (h >> 4) & 1;
    int kk   = h & 15;
    int tig  = (kk & 7) >> 1;
    int reg  = kk >> 3;
    int lane = gid * 4 + tig;
    size_t idx = (((((size_t)(layer * 4 + nb) * 8 + kchunk) * 2 + ks) * 16 + nt) * 32 + lane) * 2 + reg;
    g_wf_hi[idx] = (uint32_t)h0 | ((uint32_t)h1 << 16);
    g_wf_lo[idx] = (uint32_t)l0 | ((uint32_t)l1 << 16);
}

// ---------------------------------------------------------------------------
// Encoder: g_h[m, n] = x[m, :64] @ enc_w[:, n] + enc_b[n]  (fp32 SIMT, small)
// ---------------------------------------------------------------------------
__global__ __launch_bounds__(256) void encoder_kernel(
        const float* __restrict__ X, const float* __restrict__ W,
        const float* __restrict__ bias) {
    __shared__ float As[64][36];
    __shared__ float Bs[32][68];
    int row0 = blockIdx.x * 64;
    int n0   = blockIdx.y * 64;
    int tid = threadIdx.x;
    int tx = tid & 15, ty = tid >> 4;
    float acc[4][4] = {};
    for (int k0 = 0; k0 < DIN; k0 += 32) {
        #pragma unroll
        for (int p = 0; p < 2; p++) {
            int q = tid + p * 256;
            int r = q >> 3, kq = q & 7;
            float4 v = *(const float4*)&X[(row0 + r) * DIN + k0 + kq * 4];
            *(float4*)&As[r][kq * 4] = v;
        }
        #pragma unroll
        for (int p = 0; p < 2; p++) {
            int q = tid + p * 256;
            int kk = q >> 4, nq = q & 15;
            float4 v = *(const float4*)&W[(k0 + kk) * HH + n0 + nq * 4];
            *(float4*)&Bs[kk][nq * 4] = v;
        }
        __syncthreads();
        #pragma unroll
        for (int k = 0; k < 32; k++) {
            float a[4];
            #pragma unroll
            for (int i = 0; i < 4; i++) a[i] = As[ty * 4 + i][k];
            float4 bv = *(const float4*)&Bs[k][tx * 4];
            float bj[4] = {bv.x, bv.y, bv.z, bv.w};
            #pragma unroll
            for (int i = 0; i < 4; i++)
                #pragma unroll
                for (int j = 0; j < 4; j++)
                    acc[i][j] = fmaf(a[i], bj[j], acc[i][j]);
        }
        __syncthreads();
    }
    #pragma unroll
    for (int i = 0; i < 4; i++) {
        int m = row0 + ty * 4 + i;
        #pragma unroll
        for (int j = 0; j < 4; j++) {
            int n = n0 + tx * 4 + j;
            g_h[m * HH + n] = acc[i][j] + bias[n];
        }
    }
}

// ---------------------------------------------------------------------------
// Scan phase 1 (packed f32x2): per-chunk local recurrence from zero state.
// grid (B, H/16, NCHUNK-1), block 128.
// ---------------------------------------------------------------------------
__global__ __launch_bounds__(128) void scan_p1(
        const float* __restrict__ log_dt, const float* __restrict__ log_A_real,
        const float* __restrict__ A_imag, int layer) {
    __shared__ float s_in[128 * 16];
    int b   = blockIdx.x;
    int ch0 = blockIdx.y * 16;
    int chunk = blockIdx.z;
    int tid = threadIdx.x;
    int warp = tid >> 5, lane = tid & 31;
    int g = lane >> 3, j = lane & 7;
    int c_local = warp * 4 + g;
    int ch = ch0 + c_local;

    float dt = expf(log_dt[layer * HH + ch]);
    float wr[4], wi[4];
    #pragma unroll
    for (int k = 0; k < 4; k++) {
        int n = j * 4 + k;
        int idx = (layer * HH + ch) * NH + n;
        float Are = -expf(log_A_real[idx]);
        float Aim = A_imag[idx];
        float er  = expf(dt * Are);
        wr[k] = er * cosf(dt * Aim);
        wi[k] = er * sinf(dt * Aim);
    }
    u64 wre2[2], wim2[2], nwim2[2], sre2[2], sim2[2];
    #pragma unroll
    for (int g2 = 0; g2 < 2; g2++) {
        wre2[g2]  = pk2(wr[g2 * 2], wr[g2 * 2 + 1]);
        wim2[g2]  = pk2(wi[g2 * 2], wi[g2 * 2 + 1]);
        nwim2[g2] = pk2(-wi[g2 * 2], -wi[g2 * 2 + 1]);
        sre2[g2] = 0ull; sim2[g2] = 0ull;
    }

    const float* hin = g_h + (size_t)b * LL * HH + (size_t)chunk * CLEN * HH;
    #pragma unroll
    for (int p = 0; p < 4; p++) {
        int q = tid + p * 128;
        int t = q >> 2, cq = q & 3;
        float4 v = *(const float4*)&hin[t * HH + ch0 + cq * 4];
        *(float4*)&s_in[t * 16 + cq * 4] = v;
    }
    __syncthreads();
    #pragma unroll 8
    for (int t = 0; t < CLEN; t++) {
        float u = s_in[t * 16 + c_local];
        u64 u2 = pk2(u, u);
        #pragma unroll
        for (int g2 = 0; g2 < 2; g2++) {
            u64 nr = fma2(wre2[g2], sre2[g2], u2);
            nr = fma2(nwim2[g2], sim2[g2], nr);
            u64 ni = fma2(wre2[g2], sim2[g2], 0ull);
            ni = fma2(wim2[g2], sre2[g2], ni);
            sre2[g2] = nr; sim2[g2] = ni;
        }
    }
    size_t cbase = ((size_t)(chunk * BB + b) * HH + ch) * NH + j * 4;
    #pragma unroll
    for (int g2 = 0; g2 < 2; g2++) {
        float r0, r1, i0, i1;
        upk2(r0, r1, sre2[g2]);
        upk2(i0, i1, sim2[g2]);
        g_carry[cbase + g2 * 2 + 0] = make_float2(r0, i0);
        g_carry[cbase + g2 * 2 + 1] = make_float2(r1, i1);
    }
}

// ---------------------------------------------------------------------------
// Scan combine: sequentially propagate carries across chunks.
// ---------------------------------------------------------------------------
__global__ __launch_bounds__(256) void scan_comb(
        const float* __restrict__ log_dt, const float* __restrict__ log_A_real,
        const float* __restrict__ A_imag, int layer) {
    int gi = blockIdx.x * 256 + threadIdx.x;     // (b*HH + ch)*NH + n
    int n  = gi & 31;
    int ch = (gi >> 5) & 255;
    float dt = expf(log_dt[layer * HH + ch]);
    int idxp = (layer * HH + ch) * NH + n;
    float Are = -expf(log_A_real[idxp]);
    float Aim = A_imag[idxp];
    float er  = expf((float)CLEN * dt * Are);
    float ang = (float)CLEN * dt * Aim;
    float wp_re = er * cosf(ang);
    float wp_im = er * sinf(ang);
    float cs_re = 0.0f, cs_im = 0.0f;
    #pragma unroll
    for (int c = 0; c < NCHUNK; c++) {
        size_t idx = (size_t)c * (BB * HH * NH) + gi;
        float2 se = g_carry[idx];
        g_carry[idx] = make_float2(cs_re, cs_im);
        float nr = wp_re * cs_re - wp_im * cs_im + se.x;
        float ni = wp_re * cs_im + wp_im * cs_re + se.y;
        cs_re = nr; cs_im = ni;
    }
}

// ---------------------------------------------------------------------------
// Scan phase 2 (packed f32x2): per-chunk scan from true carry; fused D-skip +
// GELU + bf16x3 fragment emission (smem-staged, coalesced STG.128).
// grid (B, H/16, NCHUNK), block 128.
// ---------------------------------------------------------------------------
__global__ __launch_bounds__(128) void scan_p2(
        const float* __restrict__ log_dt, const float* __restrict__ C_re,
        const float* __restrict__ C_im,   const float* __restrict__ log_A_real,
        const float* __restrict__ A_imag, const float* __restrict__ D_skip,
        int layer) {
    __shared__ float s_in [128 * 16];
    __shared__ float s_out[128 * 16];
    __shared__ uint32_t s_fh[1024];
    __shared__ uint32_t s_fl[1024];
    int b   = blockIdx.x;
    int ch0 = blockIdx.y * 16;
    int chunk = blockIdx.z;
    int tid = threadIdx.x;
    int warp = tid >> 5, lane = tid & 31;
    int g = lane >> 3, j = lane & 7;
    int c_local = warp * 4 + g;
    int ch = ch0 + c_local;

    float dt  = expf(log_dt[layer * HH + ch]);
    float dsk = D_skip[layer * HH + ch];
    float wr[4], wi[4], cr[4], ci[4], sr[4], si[4];
    size_t cbase = ((size_t)(chunk * BB + b) * HH + ch) * NH + j * 4;
    #pragma unroll
    for (int k = 0; k < 4; k++) {
        int n = j * 4 + k;
        int idx = (layer * HH + ch) * NH + n;
        float Are = -expf(log_A_real[idx]);
        float Aim = A_imag[idx];
        float er  = expf(dt * Are);
        float wre = er * cosf(dt * Aim);
        float wim = er * sinf(dt * Aim);
        wr[k] = wre; wi[k] = wim;
        float nre = wre - 1.0f, nim = wim;
        float inv = 1.0f / (Are * Are + Aim * Aim);
        float ire = Are * inv, iim = -Aim * inv;
        float tre = nre * ire - nim * iim;
        float tim = nre * iim + nim * ire;
        float cre = C_re[idx], cim = C_im[idx];
        cr[k] = 2.0f * (cre * tre - cim * tim);
        ci[k] = 2.0f * (cre * tim + cim * tre);
        float2 cs = (chunk == 0) ? make_float2(0.0f, 0.0f) : g_carry[cbase + k];
        sr[k] = cs.x; si[k] = cs.y;
    }
    u64 wre2[2], wim2[2], nwim2[2], ckre2[2], nckim2[2], sre2[2], sim2[2];
    #pragma unroll
    for (int g2 = 0; g2 < 2; g2++) {
        wre2[g2]   = pk2(wr[g2 * 2], wr[g2 * 2 + 1]);
        wim2[g2]   = pk2(wi[g2 * 2], wi[g2 * 2 + 1]);
        nwim2[g2]  = pk2(-wi[g2 * 2], -wi[g2 * 2 + 1]);
        ckre2[g2]  = pk2(cr[g2 * 2], cr[g2 * 2 + 1]);
        nckim2[g2] = pk2(-ci[g2 * 2], -ci[g2 * 2 + 1]);
        sre2[g2]   = pk2(sr[g2 * 2], sr[g2 * 2 + 1]);
        sim2[g2]   = pk2(si[g2 * 2], si[g2 * 2 + 1]);
    }

    const float* hin = g_h + (size_t)b * LL * HH + (size_t)chunk * CLEN * HH;

    #pragma unroll
    for (int p = 0; p < 4; p++) {
        int q = tid + p * 128;
        int t = q >> 2, cq = q & 3;
        float4 v = *(const float4*)&hin[t * HH + ch0 + cq * 4];
        *(float4*)&s_in[t * 16 + cq * 4] = v;
    }
    __syncthreads();
    #pragma unroll 4
    for (int t = 0; t < CLEN; t++) {
        float u = s_in[t * 16 + c_local];
        u64 u2 = pk2(u, u);
        u64 pacc2 = 0ull;
        #pragma unroll
        for (int g2 = 0; g2 < 2; g2++) {
            u64 nr = fma2(wre2[g2], sre2[g2], u2);
            nr = fma2(nwim2[g2], sim2[g2], nr);
            u64 ni = fma2(wre2[g2], sim2[g2], 0ull);
            ni = fma2(wim2[g2], sre2[g2], ni);
            sre2[g2] = nr; sim2[g2] = ni;
            pacc2 = fma2(ckre2[g2], nr, pacc2);
            pacc2 = fma2(nckim2[g2], ni, pacc2);
        }
        float pa, pb;
        upk2(pa, pb, pacc2);
        float pacc = pa + pb;
        pacc += __shfl_xor_sync(0xffffffffu, pacc, 1);
        pacc += __shfl_xor_sync(0xffffffffu, pacc, 2);
        pacc += __shfl_xor_sync(0xffffffffu, pacc, 4);
        if (j == 0)
            s_out[t * 16 + c_local] = fmaf(u, dsk, pacc);
    }
    __syncthreads();
    // GELU + bf16x3 split + pack into staged fragment slice
    #pragma unroll
    for (int p = 0; p < 4; p++) {
        int q = tid + p * 128;
        int t = q >> 2, cq = q & 3;
        float4 v = *(const float4*)&s_out[t * 16 + cq * 4];
        v.x = 0.5f * v.x * (1.0f + erff(v.x * 0.70710678118654752f));
        v.y = 0.5f * v.y * (1.0f + erff(v.y * 0.70710678118654752f));
        v.z = 0.5f * v.z * (1.0f + erff(v.z * 0.70710678118654752f));
        v.w = 0.5f * v.w * (1.0f + erff(v.w * 0.70710678118654752f));
        int mtile  = t >> 4;
        int rowsel = (t >> 3) & 1;
        int gid    = t & 7;
        int kk     = cq * 4;
        int tig0   = (kk & 7) >> 1;
        int reg    = rowsel + ((kk >> 3) << 1);
        int base   = (mtile * 32 + gid * 4 + tig0) * 4 + reg;
        unsigned short hx = bfu(v.x), hy = bfu(v.y), hz = bfu(v.z), hw = bfu(v.w);
        unsigned short lx = bfu(v.x - bff(hx)), ly = bfu(v.y - bff(hy));
        unsigned short lz = bfu(v.z - bff(hz)), lw = bfu(v.w - bff(hw));
        s_fh[base]     = (uint32_t)hx | ((uint32_t)hy << 16);
        s_fh[base + 4] = (uint32_t)hz | ((uint32_t)hw << 16);
        s_fl[base]     = (uint32_t)lx | ((uint32_t)ly << 16);
        s_fl[base + 4] = (uint32_t)lz | ((uint32_t)lw << 16);
    }
    __syncthreads();
    int mblk   = (b * LL + chunk * CLEN) >> 7;
    int kchunk = ch0 >> 5;
    int ks     = (ch0 >> 4) & 1;
    size_t gb = (size_t)mblk * 16384 + (size_t)(kchunk * 2 + ks) * 1024;
    #pragma unroll
    for (int p = 0; p < 2; p++) {
        int i = (tid + p * 128) * 4;
        *(uint4*)&g_af_hi[gb + i] = *(const uint4*)&s_fh[i];
        *(uint4*)&g_af_lo[gb + i] = *(const uint4*)&s_fl[i];
    }
}

// ---------------------------------------------------------------------------
// bf16x3 warp-MMA GEMM, register-GLU epilogue, 3-stage cp.async pipeline.
// ---------------------------------------------------------------------------
#define GEMM_SMEM 98304
__global__ __launch_bounds__(256, 2) void gemm_glu_tc(
        const float* __restrict__ bias_all, int layer) {
    extern __shared__ uint32_t sm[];
    int tid = threadIdx.x, lane = tid & 31, wid = tid >> 5;
    int wm = wid & 3, wn = wid >> 2;
    int mb = blockIdx.x, nb = blockIdx.y;
    uint32_t sbase = smem_u32(sm);

    const uint32_t* Ah = g_af_hi + (size_t)mb * 16384;
    const uint32_t* Al = g_af_lo + (size_t)mb * 16384;
    const uint32_t* Bh = g_wf_hi + (size_t)(layer * 4 + nb) * 16384;
    const uint32_t* Bl = g_wf_lo + (size_t)(layer * 4 + nb) * 16384;

    float acca[2][4][4] = {};
    float accg[2][4][4] = {};

    #pragma unroll
    for (int st = 0; st < 3; st++) {
        uint32_t db = sbase + st * 32768u;
        #pragma unroll
        for (int ii = 0; ii < 2; ii++) {
            int c = tid + ii * 256;
            cp16(db +          c * 16, Ah + (size_t)st * 2048 + c * 4);
            cp16(db +  8192u + c * 16, Al + (size_t)st * 2048 + c * 4);
            cp16(db + 16384u + c * 16, Bh + (size_t)st * 2048 + c * 4);
            cp16(db + 24576u + c * 16, Bl + (size_t)st * 2048 + c * 4);
        }
        asm volatile("cp.async.commit_group;");
    }

    for (int kc = 0; kc < 8; kc++) {
        asm volatile("cp.async.wait_group 2;");
        __syncthreads();
        int stg = kc % 3;
        const uint32_t* sAh = sm + stg * 8192;
        const uint32_t* sAl = sAh + 2048;
        const uint32_t* sBh = sAh + 4096;
        const uint32_t* sBl = sAh + 6144;
        #pragma unroll
        for (int ks = 0; ks < 2; ks++) {
            uint32_t ah[2][4], al[2][4];
            #pragma unroll
            for (int mt = 0; mt < 2; mt++) {
                int base = (ks * 8 + wm * 2 + mt) * 128 + lane * 4;
                uint4 qh = *(const uint4*)&sAh[base];
                uint4 ql = *(const uint4*)&sAl[base];
                ah[mt][0] = qh.x; ah[mt][1] = qh.y; ah[mt][2] = qh.z; ah[mt][3] = qh.w;
                al[mt][0] = ql.x; al[mt][1] = ql.y; al[mt][2] = ql.z; al[mt][3] = ql.w;
            }
            #pragma unroll
            for (int i = 0; i < 4; i++) {
                int bidx_a = ((ks * 16 +     wn * 4 + i) * 32 + lane) * 2;
                int bidx_g = ((ks * 16 + 8 + wn * 4 + i) * 32 + lane) * 2;
                uint2 bha = *(const uint2*)&sBh[bidx_a];
                uint2 bla = *(const uint2*)&sBl[bidx_a];
                uint2 bhg = *(const uint2*)&sBh[bidx_g];
                uint2 blg = *(const uint2*)&sBl[bidx_g];
                #pragma unroll
                for (int mt = 0; mt < 2; mt++) {
                    mma_bf16(acca[mt][i], ah[mt], bha.x, bha.y);
                    mma_bf16(acca[mt][i], al[mt], bha.x, bha.y);
                    mma_bf16(acca[mt][i], ah[mt], bla.x, bla.y);
                    mma_bf16(accg[mt][i], ah[mt], bhg.x, bhg.y);
                    mma_bf16(accg[mt][i], al[mt], bhg.x, bhg.y);
                    mma_bf16(accg[mt][i], ah[mt], blg.x, blg.y);
                }
            }
        }
        __syncthreads();
        if (kc < 5) {
            int st = kc + 3;
            uint32_t db = sbase + (st % 3) * 32768u;
            #pragma unroll
            for (int ii = 0; ii < 2; ii++) {
                int c = tid + ii * 256;
                cp16(db +          c * 16, Ah + (size_t)st * 2048 + c * 4);
                cp16(db +  8192u + c * 16, Al + (size_t)st * 2048 + c * 4);
                cp16(db + 16384u + c * 16, Bh + (size_t)st * 2048 + c * 4);
                cp16(db + 24576u + c * 16, Bl + (size_t)st * 2048 + c * 4);
            }
            asm volatile("cp.async.commit_group;");
        } else {
            asm volatile("cp.async.commit_group;");
        }
    }

    const float* brow = bias_all + layer * 512;
    #pragma unroll
    for (int i = 0; i < 4; i++) {
        int cbase = nb * 64 + wn * 32 + i * 8 + (lane & 3) * 2;
        float ba0 = brow[cbase],       ba1 = brow[cbase + 1];
        float bg0 = brow[cbase + 256], bg1 = brow[cbase + 257];
        #pragma unroll
        for (int mt = 0; mt < 2; mt++) {
            int r0 = mb * 128 + wm * 32 + mt * 16 + (lane >> 2);
            #pragma unroll
            for (int half = 0; half < 2; half++) {
                size_t m = (size_t)r0 + half * 8;
                float a0 = acca[mt][i][half * 2 + 0] + ba0;
                float a1 = acca[mt][i][half * 2 + 1] + ba1;
                float g0 = accg[mt][i][half * 2 + 0] + bg0;
                float g1 = accg[mt][i][half * 2 + 1] + bg1;
                float2 hres = *(const float2*)&g_h[m * HH + cbase];
                float2 zo;
                zo.x = a0 / (1.0f + expf(-g0)) + hres.x;
                zo.y = a1 / (1.0f + expf(-g1)) + hres.y;
                *(float2*)&g_zr[m * HH + cbase] = zo;
            }
        }
    }
}

// ---------------------------------------------------------------------------
// LayerNorm over H=256: g_h = LN(g_zr)*gamma + beta.  One warp per row.
// ---------------------------------------------------------------------------
__global__ __launch_bounds__(256) void ln_kernel(
        const float* __restrict__ lng, const float* __restrict__ lnb, int layer) {
    int row  = blockIdx.x * 8 + (threadIdx.x >> 5);
    int lane = threadIdx.x & 31;
    const float* Z = g_zr + (size_t)row * HH;
    float4 v0 = *(const float4*)&Z[lane * 4];
    float4 v1 = *(const float4*)&Z[128 + lane * 4];
    float s  = v0.x + v0.y + v0.z + v0.w + v1.x + v1.y + v1.z + v1.w;
    float ss = v0.x*v0.x + v0.y*v0.y + v0.z*v0.z + v0.w*v0.w
             + v1.x*v1.x + v1.y*v1.y + v1.z*v1.z + v1.w*v1.w;
    #pragma unroll
    for (int o = 16; o; o >>= 1) {
        s  += __shfl_xor_sync(0xffffffffu, s,  o);
        ss += __shfl_xor_sync(0xffffffffu, ss, o);
    }
    float mean = s * (1.0f / 256.0f);
    float var  = ss * (1.0f / 256.0f) - mean * mean;
    float rstd = rsqrtf(var + 1e-5f);
    float* O = g_h + (size_t)row * HH;
    const float* G0 = &lng[layer * HH];
    const float* B0 = &lnb[layer * HH];
    float4 ga = *(const float4*)&G0[lane * 4];
    float4 gb = *(const float4*)&G0[128 + lane * 4];
    float4 ba = *(const float4*)&B0[lane * 4];
    float4 bb = *(const float4*)&B0[128 + lane * 4];
    float4 o0, o1;
    o0.x = (v0.x - mean) * rstd * ga.x + ba.x;
    o0.y = (v0.y - mean) * rstd * ga.y + ba.y;
    o0.z = (v0.z - mean) * rstd * ga.z + ba.z;
    o0.w = (v0.w - mean) * rstd * ga.w + ba.w;
    o1.x = (v1.x - mean) * rstd * gb.x + bb.x;
    o1.y = (v1.y - mean) * rstd * gb.y + bb.y;
    o1.z = (v1.z - mean) * rstd * gb.z + bb.z;
    o1.w = (v1.w - mean) * rstd * gb.w + bb.w;
    *(float4*)&O[lane * 4] = o0;
    *(float4*)&O[128 + lane * 4] = o1;
}

// ---------------------------------------------------------------------------
// Two-phase mean pool over L
// ---------------------------------------------------------------------------
__global__ __launch_bounds__(256) void pool1_kernel() {
    int b = blockIdx.x, seg = blockIdx.y, ch = threadIdx.x;
    const float* Hp = g_h + ((size_t)b * LL + (size_t)seg * 128) * HH + ch;
    float s0 = 0.f, s1 = 0.f, s2 = 0.f, s3 = 0.f;
    for (int l = 0; l < 128; l += 4) {
        s0 += Hp[(size_t)(l + 0) * HH];
        s1 += Hp[(size_t)(l + 1) * HH];
        s2 += Hp[(size_t)(l + 2) * HH];
        s3 += Hp[(size_t)(l + 3) * HH];
    }
    g_poolp[(b * 16 + seg) * HH + ch] = s0 + s1 + s2 + s3;
}
__global__ __launch_bounds__(256) void pool2_kernel() {
    int b = blockIdx.x, ch = threadIdx.x;
    float s = 0.f;
    #pragma unroll
    for (int seg = 0; seg < 16; seg++)
        s += g_poolp[(b * 16 + seg) * HH + ch];
    g_pool[b * HH + ch] = s * (1.0f / LL);
}

// ---------------------------------------------------------------------------
// Decoder MLP: 256 -> 128 relu -> 64 relu -> 32
// ---------------------------------------------------------------------------
__global__ __launch_bounds__(128) void decoder_kernel(
        const float* __restrict__ w1, const float* __restrict__ b1,
        const float* __restrict__ w2, const float* __restrict__ b2,
        const float* __restrict__ w3, const float* __restrict__ b3,
        float* __restrict__ out) {
    __shared__ float p[HH];
    __shared__ float q1[DM1];
    __shared__ float q2[DM2];
    int b = blockIdx.x, tid = threadIdx.x;
    p[tid]       = g_pool[b * HH + tid];
    p[tid + 128] = g_pool[b * HH + tid + 128];
    __syncthreads();
    {
        float s = b1[tid];
        #pragma unroll 4
        for (int k = 0; k < HH; k++) s = fmaf(p[k], w1[k * DM1 + tid], s);
        q1[tid] = fmaxf(s, 0.0f);
    }
    __syncthreads();
    if (tid < DM2) {
        float s = b2[tid];
        #pragma unroll 4
        for (int k = 0; k < DM1; k++) s = fmaf(q1[k], w2[k * DM2 + tid], s);
        q2[tid] = fmaxf(s, 0.0f);
    }
    __syncthreads();
    if (tid < DOUT) {
        float s = b3[tid];
        #pragma unroll 4
        for (int k = 0; k < DM2; k++) s = fmaf(q2[k], w3[k * DOUT + tid], s);
        out[b * DOUT + tid] = s;
    }
}

// ---------------------------------------------------------------------------
extern "C" void kernel_launch(void* const* d_in, const int* in_sizes, int n_in,
                              void* d_out, int out_size) {
    const float* x          = (const float*)d_in[0];
    const float* enc_w      = (const float*)d_in[1];
    const float* enc_b      = (const float*)d_in[2];
    const float* log_dt     = (const float*)d_in[3];
    const float* C_re       = (const float*)d_in[4];
    const float* C_im       = (const float*)d_in[5];
    const float* log_A_real = (const float*)d_in[6];
    const float* A_imag     = (const float*)d_in[7];
    const float* D_skip     = (const float*)d_in[8];
    const float* w_out      = (const float*)d_in[9];
    const float* b_out      = (const float*)d_in[10];
    const float* ln_g       = (const float*)d_in[11];
    const float* ln_b       = (const float*)d_in[12];
    const float* dec_w1     = (const float*)d_in[13];
    const float* dec_b1     = (const float*)d_in[14];
    const float* dec_w2     = (const float*)d_in[15];
    const float* dec_b2     = (const float*)d_in[16];
    const float* dec_w3     = (const float*)d_in[17];
    const float* dec_b3     = (const float*)d_in[18];
    float* out = (float*)d_out;

    cudaFuncSetAttribute(gemm_glu_tc,
                         cudaFuncAttributeMaxDynamicSharedMemorySize, GEMM_SMEM);

    prep_w_kernel<<<(NLAYERS * 512 * 128 + 255) / 256, 256>>>(w_out);
    dim3 enc_grid(MROWS / 64, HH / 64);
    encoder_kernel<<<enc_grid, 256>>>(x, enc_w, enc_b);
    dim3 p1_grid(BB, HH / 16, NCHUNK - 1);
    dim3 p2_grid(BB, HH / 16, NCHUNK);
    for (int layer = 0; layer < NLAYERS; layer++) {
        scan_p1<<<p1_grid, 128>>>(log_dt, log_A_real, A_imag, layer);
        scan_comb<<<BB * HH * NH / 256, 256>>>(log_dt, log_A_real, A_imag, layer);
        scan_p2<<<p2_grid, 128>>>(log_dt, C_re, C_im,
                                  log_A_real, A_imag, D_skip, layer);
        gemm_glu_tc<<<dim3(NMBLK, 4), 256, GEMM_SMEM>>>(b_out, layer);
        ln_kernel<<<MROWS / 8, 256>>>(ln_g, ln_b, layer);
    }
    pool1_kernel<<<dim3(BB, 16), 256>>>();
    pool2_kernel<<<BB, 256>>>();
    decoder_kernel<<<BB, 128>>>(dec_w1, dec_b1, dec_w2, dec_b2, dec_w3, dec_b3, out);
}